// round 2
// baseline (speedup 1.0000x reference)
#include <cuda_runtime.h>
#include <math.h>

// ---------------- problem constants ----------------
constexpr int Hdim   = 256;
constexpr int INdim  = 64;
constexpr int HD2    = 128;
constexpr int OUTdim = 12;
constexpr int NLAY   = 3;
constexpr int NGRAPH = 64;
constexpr int NMAX   = 50000;

// ---------------- scratch (device globals, no allocation) ----------------
__device__ float  g_bufA[(size_t)NMAX * Hdim];   // h / agg
__device__ float  g_bufB[(size_t)NMAX * Hdim];   // hw
__device__ float  g_dis[NMAX];                   // rsqrt(deg)
__device__ double g_stats[2 * Hdim];             // sum, sumsq
__device__ float  g_scale[Hdim];
__device__ float  g_shift[Hdim];
__device__ float  g_pool[NGRAPH * Hdim];

// ---------------- degree / norm ----------------
__global__ void deg_init_k(float* dis, int N) {
    int i = blockIdx.x * blockDim.x + threadIdx.x;
    if (i < N) dis[i] = 1.0f;  // self-loop
}

__global__ void deg_acc_k(const int* __restrict__ coli, float* dis, int E) {
    int i = blockIdx.x * blockDim.x + threadIdx.x;
    int stride = gridDim.x * blockDim.x;
    for (int e = i; e < E; e += stride) atomicAdd(&dis[coli[e]], 1.0f);
}

__global__ void deg_rsqrt_k(float* dis, int N) {
    int i = blockIdx.x * blockDim.x + threadIdx.x;
    if (i < N) dis[i] = rsqrtf(dis[i]);
}

// ---------------- SGEMM: C[M,256] = A[M,K] @ B[K,256] (+bias) ----------------
// 128x128 block tile, BK=8, 256 threads, 8x8 per-thread microtile.
__global__ __launch_bounds__(256, 2)
void gemm_k(const float* __restrict__ A, const float* __restrict__ B,
            const float* __restrict__ bias, float* __restrict__ C,
            int M, int K)
{
    constexpr int BM = 128, BN = 128, BK = 8;
    __shared__ float As[BK][BM];
    __shared__ float Bs[BK][BN];

    int tid = threadIdx.x;
    int cx = tid % 16;       // col group (x8)
    int ry = tid / 16;       // row group (x8)
    int rowBase = blockIdx.y * BM;
    int colBase = blockIdx.x * BN;

    float acc[8][8];
#pragma unroll
    for (int i = 0; i < 8; i++)
#pragma unroll
        for (int j = 0; j < 8; j++) acc[i][j] = 0.0f;

    int aRow = tid >> 1;          // 0..127
    int aCol = (tid & 1) * 4;     // 0 or 4
    int bRow = tid >> 5;          // 0..7
    int bCol = (tid & 31) * 4;    // 0..124

    bool aValid = (rowBase + aRow) < M;
    const float* Aptr = A + (size_t)(rowBase + aRow) * K + aCol;
    const float* Bptr = B + (size_t)bRow * 256 + colBase + bCol;

    for (int k0 = 0; k0 < K; k0 += BK) {
        float4 av = aValid ? *(const float4*)(Aptr + k0) : make_float4(0.f, 0.f, 0.f, 0.f);
        float4 bv = *(const float4*)(Bptr + (size_t)k0 * 256);
        __syncthreads();
        As[aCol + 0][aRow] = av.x;
        As[aCol + 1][aRow] = av.y;
        As[aCol + 2][aRow] = av.z;
        As[aCol + 3][aRow] = av.w;
        *(float4*)&Bs[bRow][bCol] = bv;
        __syncthreads();
#pragma unroll
        for (int k = 0; k < BK; k++) {
            float a[8], b[8];
#pragma unroll
            for (int i = 0; i < 8; i++) a[i] = As[k][ry * 8 + i];
#pragma unroll
            for (int j = 0; j < 8; j++) b[j] = Bs[k][cx * 8 + j];
#pragma unroll
            for (int i = 0; i < 8; i++)
#pragma unroll
                for (int j = 0; j < 8; j++) acc[i][j] = fmaf(a[i], b[j], acc[i][j]);
        }
    }

#pragma unroll
    for (int i = 0; i < 8; i++) {
        int r = rowBase + ry * 8 + i;
        if (r < M) {
#pragma unroll
            for (int j = 0; j < 8; j += 4) {
                int c = colBase + cx * 8 + j;
                float4 v;
                v.x = acc[i][j];     v.y = acc[i][j + 1];
                v.z = acc[i][j + 2]; v.w = acc[i][j + 3];
                if (bias) {
                    v.x += bias[c];     v.y += bias[c + 1];
                    v.z += bias[c + 2]; v.w += bias[c + 3];
                }
                *(float4*)&C[(size_t)r * 256 + c] = v;
            }
        }
    }
}

// ---------------- agg init: self-loop + conv bias ----------------
__global__ void init_agg_k(const float* __restrict__ hw, const float* __restrict__ dis,
                           const float* __restrict__ convb, float* __restrict__ agg, int N)
{
    int idx = blockIdx.x * blockDim.x + threadIdx.x;   // over N*64 float4
    if (idx >= N * 64) return;
    int node = idx >> 6;
    int f4 = idx & 63;
    float d = dis[node];
    float sn = d * d;                 // self-loop norm = 1/deg
    float4 v = ((const float4*)hw)[idx];
    float4 b = ((const float4*)convb)[f4];
    float4 o;
    o.x = fmaf(v.x, sn, b.x);
    o.y = fmaf(v.y, sn, b.y);
    o.z = fmaf(v.z, sn, b.z);
    o.w = fmaf(v.w, sn, b.w);
    ((float4*)agg)[idx] = o;
}

// ---------------- edge scatter: warp per edge, v4 reduction atomics ----------------
__global__ void edge_scatter_k(const float* __restrict__ hw, float* __restrict__ agg,
                               const int* __restrict__ rowi, const int* __restrict__ coli,
                               const float* __restrict__ dis, int E)
{
    int w = (blockIdx.x * blockDim.x + threadIdx.x) >> 5;
    int lane = threadIdx.x & 31;
    if (w >= E) return;
    int r = __ldg(rowi + w);
    int c = __ldg(coli + w);
    float nrm = __ldg(dis + r) * __ldg(dis + c);
    const float4* src = (const float4*)(hw + (size_t)r * Hdim);
    float* dst = agg + (size_t)c * Hdim;
#pragma unroll
    for (int k = 0; k < 2; k++) {
        int i = lane + k * 32;
        float4 v = src[i];
        asm volatile("red.global.add.v4.f32 [%0], {%1,%2,%3,%4};"
                     :: "l"(dst + i * 4),
                        "f"(v.x * nrm), "f"(v.y * nrm), "f"(v.z * nrm), "f"(v.w * nrm)
                     : "memory");
    }
}

// ---------------- batchnorm ----------------
__global__ void zero_d_k(double* p, int n) {
    int i = blockIdx.x * blockDim.x + threadIdx.x;
    if (i < n) p[i] = 0.0;
}

__global__ void zero_f_k(float* p, int n) {
    int i = blockIdx.x * blockDim.x + threadIdx.x;
    if (i < n) p[i] = 0.0f;
}

__global__ void bn_stats_k(const float* __restrict__ agg, double* __restrict__ stats, int N) {
    int f = threadIdx.x;            // 256 threads, one feature each
    int chunk = (N + gridDim.x - 1) / gridDim.x;
    int r0 = blockIdx.x * chunk;
    int r1 = min(N, r0 + chunk);
    float s = 0.f, s2 = 0.f;
    for (int r = r0; r < r1; r++) {
        float v = agg[(size_t)r * Hdim + f];
        s += v;
        s2 = fmaf(v, v, s2);
    }
    atomicAdd(&stats[f], (double)s);
    atomicAdd(&stats[Hdim + f], (double)s2);
}

__global__ void bn_final_k(const double* __restrict__ stats,
                           const float* __restrict__ gamma, const float* __restrict__ beta,
                           float* __restrict__ scale, float* __restrict__ shift, int N)
{
    int f = threadIdx.x;
    double mean = stats[f] / N;
    double var = stats[Hdim + f] / N - mean * mean;
    float sc = gamma[f] * rsqrtf((float)var + 1e-5f);
    scale[f] = sc;
    shift[f] = beta[f] - (float)mean * sc;
}

__global__ void bn_apply_k(float* __restrict__ h, const float* __restrict__ scale,
                           const float* __restrict__ shift, int N)
{
    int idx = blockIdx.x * blockDim.x + threadIdx.x;   // over N*64 float4
    if (idx >= N * 64) return;
    int f4 = idx & 63;
    float4 v = ((float4*)h)[idx];
    float4 sc = ((const float4*)scale)[f4];
    float4 sh = ((const float4*)shift)[f4];
    v.x = fmaxf(fmaf(v.x, sc.x, sh.x), 0.f);
    v.y = fmaxf(fmaf(v.y, sc.y, sh.y), 0.f);
    v.z = fmaxf(fmaf(v.z, sc.z, sh.z), 0.f);
    v.w = fmaxf(fmaf(v.w, sc.w, sh.w), 0.f);
    ((float4*)h)[idx] = v;
}

// ---------------- global add pool (batch sorted) ----------------
__global__ void pool_k(const float* __restrict__ h, const int* __restrict__ batch,
                       float* __restrict__ g, int N)
{
    constexpr int CH = 256;
    int f = threadIdx.x;
    int r0 = blockIdx.x * CH;
    int r1 = min(N, r0 + CH);
    if (r0 >= N) return;
    int cur = batch[r0];
    float s = 0.f;
    for (int r = r0; r < r1; r++) {
        int b = batch[r];
        if (b != cur) {
            atomicAdd(&g[cur * Hdim + f], s);
            s = 0.f;
            cur = b;
        }
        s += h[(size_t)r * Hdim + f];
    }
    atomicAdd(&g[cur * Hdim + f], s);
}

// ---------------- MLP head: one block per graph ----------------
__global__ void head_k(const float* __restrict__ g, const float* __restrict__ w1,
                       const float* __restrict__ b1, const float* __restrict__ w2,
                       const float* __restrict__ b2, float* __restrict__ out)
{
    __shared__ float gs[Hdim];
    __shared__ float zs[HD2];
    int b = blockIdx.x;
    int t = threadIdx.x;   // 128 threads
    gs[t]       = g[b * Hdim + t];
    gs[t + 128] = g[b * Hdim + t + 128];
    __syncthreads();
    float acc = b1[t];
    for (int k = 0; k < Hdim; k++) acc = fmaf(gs[k], w1[k * HD2 + t], acc);
    zs[t] = fmaxf(acc, 0.f);
    __syncthreads();
    if (t < OUTdim) {
        float o = b2[t];
        for (int k = 0; k < HD2; k++) o = fmaf(zs[k], w2[k * OUTdim + t], o);
        out[b * OUTdim + t] = o;
    }
}

// ---------------- launch ----------------
extern "C" void kernel_launch(void* const* d_in, const int* in_sizes, int n_in,
                              void* d_out, int out_size)
{
    const float* x       = (const float*)d_in[0];
    const int*   ei      = (const int*)d_in[1];
    const int*   batch   = (const int*)d_in[2];
    const float* node_w  = (const float*)d_in[3];
    const float* node_b  = (const float*)d_in[4];
    const float* conv_w  = (const float*)d_in[5];
    const float* conv_b  = (const float*)d_in[6];
    const float* bn_g    = (const float*)d_in[7];
    const float* bn_b    = (const float*)d_in[8];
    const float* head_w1 = (const float*)d_in[9];
    const float* head_b1 = (const float*)d_in[10];
    const float* head_w2 = (const float*)d_in[11];
    const float* head_b2 = (const float*)d_in[12];
    float* out = (float*)d_out;

    int N = in_sizes[0] / INdim;
    int E = in_sizes[1] / 2;
    const int* rowi = ei;
    const int* coli = ei + E;

    float *bufA, *bufB, *dis, *scale, *shift, *pool;
    double* stats;
    cudaGetSymbolAddress((void**)&bufA, g_bufA);
    cudaGetSymbolAddress((void**)&bufB, g_bufB);
    cudaGetSymbolAddress((void**)&dis, g_dis);
    cudaGetSymbolAddress((void**)&stats, g_stats);
    cudaGetSymbolAddress((void**)&scale, g_scale);
    cudaGetSymbolAddress((void**)&shift, g_shift);
    cudaGetSymbolAddress((void**)&pool, g_pool);

    // degree / normalization
    deg_init_k<<<(N + 255) / 256, 256>>>(dis, N);
    deg_acc_k<<<592, 256>>>(coli, dis, E);
    deg_rsqrt_k<<<(N + 255) / 256, 256>>>(dis, N);

    dim3 ggrid(2, (N + 127) / 128);

    // node embedding: h = x @ node_w + node_b  -> bufA
    gemm_k<<<ggrid, 256>>>(x, node_w, node_b, bufA, N, INdim);

    int nElem4 = N * (Hdim / 4);
    for (int l = 0; l < NLAY; l++) {
        // hw = h @ conv_w[l] -> bufB
        gemm_k<<<ggrid, 256>>>(bufA, conv_w + (size_t)l * Hdim * Hdim, nullptr, bufB, N, Hdim);
        // agg init (self-loop + bias) -> bufA, then edge scatter into bufA
        init_agg_k<<<(nElem4 + 255) / 256, 256>>>(bufB, dis, conv_b + l * Hdim, bufA, N);
        edge_scatter_k<<<(E * 32 + 255) / 256, 256>>>(bufB, bufA, rowi, coli, dis, E);
        // batchnorm + relu in place
        zero_d_k<<<2, 256>>>(stats, 2 * Hdim);
        bn_stats_k<<<200, 256>>>(bufA, stats, N);
        bn_final_k<<<1, 256>>>(stats, bn_g + l * Hdim, bn_b + l * Hdim, scale, shift, N);
        bn_apply_k<<<(nElem4 + 255) / 256, 256>>>(bufA, scale, shift, N);
    }

    // global add pool + head
    zero_f_k<<<(NGRAPH * Hdim + 255) / 256, 256>>>(pool, NGRAPH * Hdim);
    pool_k<<<(N + 255) / 256, 256>>>(bufA, batch, pool, N);
    head_k<<<NGRAPH, HD2>>>(pool, head_w1, head_b1, head_w2, head_b2, out);
}

// round 3
// speedup vs baseline: 1.2210x; 1.2210x over previous
#include <cuda_runtime.h>
#include <math.h>

// ---------------- problem constants ----------------
constexpr int Hdim   = 256;
constexpr int INdim  = 64;
constexpr int HD2    = 128;
constexpr int OUTdim = 12;
constexpr int NLAY   = 3;
constexpr int NGRAPH = 64;
constexpr int NMAX   = 50000;
constexpr int EMAX   = 600000;
constexpr int SCAN_B = 512;
constexpr int MAXBLK1 = (NMAX + SCAN_B - 1) / SCAN_B;   // 98

// ---------------- scratch (device globals, no allocation) ----------------
__device__ float  g_bufA[(size_t)NMAX * Hdim];   // h / agg
__device__ float  g_bufB[(size_t)NMAX * Hdim];   // hw
__device__ float  g_dis[NMAX];                   // rsqrt(deg)
__device__ int    g_cnt[NMAX];                   // in-edge counts (excl self)
__device__ int    g_rowptr[NMAX + 1];
__device__ int    g_cursor[NMAX];
__device__ int    g_partial[NMAX];
__device__ int    g_bsum[MAXBLK1 + 1];
__device__ int    g_csr_src[EMAX];
__device__ float  g_csr_nrm[EMAX];
__device__ double g_stats[2 * Hdim];             // sum, sumsq
__device__ float  g_scale[Hdim];
__device__ float  g_shift[Hdim];
__device__ float  g_pool[NGRAPH * Hdim];

// ---------------- degree / CSR build ----------------
__global__ void zero_i_k(int* p, int n) {
    int i = blockIdx.x * blockDim.x + threadIdx.x;
    if (i < n) p[i] = 0;
}

__global__ void count_k(const int* __restrict__ coli, int* __restrict__ cnt, int E) {
    int i = blockIdx.x * blockDim.x + threadIdx.x;
    int stride = gridDim.x * blockDim.x;
    for (int e = i; e < E; e += stride) atomicAdd(&cnt[coli[e]], 1);
}

// block-level inclusive scan -> exclusive partials + per-block totals
__global__ void scan1_k(const int* __restrict__ cnt, int* __restrict__ partial,
                        int* __restrict__ bsum, int N)
{
    __shared__ int sh[SCAN_B];
    int t = threadIdx.x;
    int i = blockIdx.x * SCAN_B + t;
    int v = (i < N) ? cnt[i] : 0;
    sh[t] = v;
    __syncthreads();
#pragma unroll
    for (int off = 1; off < SCAN_B; off <<= 1) {
        int add = (t >= off) ? sh[t - off] : 0;
        __syncthreads();
        sh[t] += add;
        __syncthreads();
    }
    if (i < N) partial[i] = sh[t] - v;           // exclusive within block
    if (t == SCAN_B - 1) bsum[blockIdx.x] = sh[t];
}

// single-block exclusive scan of block sums (nb <= 512)
__global__ void scan2_k(int* __restrict__ bsum, int nb) {
    __shared__ int sh[SCAN_B];
    int t = threadIdx.x;
    int v = (t < nb) ? bsum[t] : 0;
    sh[t] = v;
    __syncthreads();
#pragma unroll
    for (int off = 1; off < SCAN_B; off <<= 1) {
        int add = (t >= off) ? sh[t - off] : 0;
        __syncthreads();
        sh[t] += add;
        __syncthreads();
    }
    if (t < nb) bsum[t] = sh[t] - v;             // exclusive
}

// rowptr = partial + bsum[blk]; cursor = rowptr; dis = rsqrt(cnt+1)
__global__ void scan3_k(const int* __restrict__ partial, const int* __restrict__ bsum,
                        const int* __restrict__ cnt, int* __restrict__ rowptr,
                        int* __restrict__ cursor, float* __restrict__ dis, int N, int E)
{
    int i = blockIdx.x * blockDim.x + threadIdx.x;
    if (i < N) {
        int rp = partial[i] + bsum[i / SCAN_B];
        rowptr[i] = rp;
        cursor[i] = rp;
        dis[i] = rsqrtf((float)(cnt[i] + 1));    // +1 self-loop
    }
    if (i == 0) rowptr[N] = E;
}

__global__ void fill_k(const int* __restrict__ rowi, const int* __restrict__ coli,
                       const float* __restrict__ dis, int* __restrict__ cursor,
                       int* __restrict__ csr_src, float* __restrict__ csr_nrm, int E)
{
    int i = blockIdx.x * blockDim.x + threadIdx.x;
    int stride = gridDim.x * blockDim.x;
    for (int e = i; e < E; e += stride) {
        int r = rowi[e], c = coli[e];
        int slot = atomicAdd(&cursor[c], 1);
        csr_src[slot] = r;
        csr_nrm[slot] = dis[r] * dis[c];
    }
}

// ---------------- SGEMM: C[M,256] = A[M,K] @ B[K,256] (+bias) ----------------
__global__ __launch_bounds__(256, 2)
void gemm_k(const float* __restrict__ A, const float* __restrict__ B,
            const float* __restrict__ bias, float* __restrict__ C,
            int M, int K)
{
    constexpr int BM = 128, BN = 128, BK = 8;
    __shared__ float As[BK][BM];
    __shared__ float Bs[BK][BN];

    int tid = threadIdx.x;
    int cx = tid % 16;
    int ry = tid / 16;
    int rowBase = blockIdx.y * BM;
    int colBase = blockIdx.x * BN;

    float acc[8][8];
#pragma unroll
    for (int i = 0; i < 8; i++)
#pragma unroll
        for (int j = 0; j < 8; j++) acc[i][j] = 0.0f;

    int aRow = tid >> 1;
    int aCol = (tid & 1) * 4;
    int bRow = tid >> 5;
    int bCol = (tid & 31) * 4;

    bool aValid = (rowBase + aRow) < M;
    const float* Aptr = A + (size_t)(rowBase + aRow) * K + aCol;
    const float* Bptr = B + (size_t)bRow * 256 + colBase + bCol;

    for (int k0 = 0; k0 < K; k0 += BK) {
        float4 av = aValid ? *(const float4*)(Aptr + k0) : make_float4(0.f, 0.f, 0.f, 0.f);
        float4 bv = *(const float4*)(Bptr + (size_t)k0 * 256);
        __syncthreads();
        As[aCol + 0][aRow] = av.x;
        As[aCol + 1][aRow] = av.y;
        As[aCol + 2][aRow] = av.z;
        As[aCol + 3][aRow] = av.w;
        *(float4*)&Bs[bRow][bCol] = bv;
        __syncthreads();
#pragma unroll
        for (int k = 0; k < BK; k++) {
            float a[8], b[8];
#pragma unroll
            for (int i = 0; i < 8; i++) a[i] = As[k][ry * 8 + i];
#pragma unroll
            for (int j = 0; j < 8; j++) b[j] = Bs[k][cx * 8 + j];
#pragma unroll
            for (int i = 0; i < 8; i++)
#pragma unroll
                for (int j = 0; j < 8; j++) acc[i][j] = fmaf(a[i], b[j], acc[i][j]);
        }
    }

#pragma unroll
    for (int i = 0; i < 8; i++) {
        int r = rowBase + ry * 8 + i;
        if (r < M) {
#pragma unroll
            for (int j = 0; j < 8; j += 4) {
                int c = colBase + cx * 8 + j;
                float4 v;
                v.x = acc[i][j];     v.y = acc[i][j + 1];
                v.z = acc[i][j + 2]; v.w = acc[i][j + 3];
                if (bias) {
                    v.x += bias[c];     v.y += bias[c + 1];
                    v.z += bias[c + 2]; v.w += bias[c + 3];
                }
                *(float4*)&C[(size_t)r * 256 + c] = v;
            }
        }
    }
}

// ---------------- aggregate: warp per node, CSR gather, no atomics ----------------
__global__ __launch_bounds__(256)
void aggregate_k(const float* __restrict__ hw, float* __restrict__ agg,
                 const int* __restrict__ rowptr, const int* __restrict__ csr_src,
                 const float* __restrict__ csr_nrm, const float* __restrict__ dis,
                 const float* __restrict__ convb, int N)
{
    int warp = (blockIdx.x * blockDim.x + threadIdx.x) >> 5;
    int lane = threadIdx.x & 31;
    if (warp >= N) return;
    int n = warp;

    float dn = __ldg(dis + n);
    float sn = dn * dn;                       // self-loop norm
    const float4* self = (const float4*)(hw + (size_t)n * Hdim);
    float4 b0 = ((const float4*)convb)[lane];
    float4 b1 = ((const float4*)convb)[lane + 32];
    float4 v0 = self[lane];
    float4 v1 = self[lane + 32];
    float4 acc0, acc1;
    acc0.x = fmaf(v0.x, sn, b0.x); acc0.y = fmaf(v0.y, sn, b0.y);
    acc0.z = fmaf(v0.z, sn, b0.z); acc0.w = fmaf(v0.w, sn, b0.w);
    acc1.x = fmaf(v1.x, sn, b1.x); acc1.y = fmaf(v1.y, sn, b1.y);
    acc1.z = fmaf(v1.z, sn, b1.z); acc1.w = fmaf(v1.w, sn, b1.w);

    int j  = __ldg(rowptr + n);
    int e1 = __ldg(rowptr + n + 1);

    // 2-edge unrolled: 4 independent float4 loads in flight
    for (; j + 1 < e1; j += 2) {
        int   ra = __ldg(csr_src + j);
        int   rb = __ldg(csr_src + j + 1);
        float na = __ldg(csr_nrm + j);
        float nb = __ldg(csr_nrm + j + 1);
        const float4* pa = (const float4*)(hw + (size_t)ra * Hdim);
        const float4* pb = (const float4*)(hw + (size_t)rb * Hdim);
        float4 a0 = pa[lane], a1 = pa[lane + 32];
        float4 c0 = pb[lane], c1 = pb[lane + 32];
        acc0.x = fmaf(a0.x, na, acc0.x); acc0.y = fmaf(a0.y, na, acc0.y);
        acc0.z = fmaf(a0.z, na, acc0.z); acc0.w = fmaf(a0.w, na, acc0.w);
        acc1.x = fmaf(a1.x, na, acc1.x); acc1.y = fmaf(a1.y, na, acc1.y);
        acc1.z = fmaf(a1.z, na, acc1.z); acc1.w = fmaf(a1.w, na, acc1.w);
        acc0.x = fmaf(c0.x, nb, acc0.x); acc0.y = fmaf(c0.y, nb, acc0.y);
        acc0.z = fmaf(c0.z, nb, acc0.z); acc0.w = fmaf(c0.w, nb, acc0.w);
        acc1.x = fmaf(c1.x, nb, acc1.x); acc1.y = fmaf(c1.y, nb, acc1.y);
        acc1.z = fmaf(c1.z, nb, acc1.z); acc1.w = fmaf(c1.w, nb, acc1.w);
    }
    if (j < e1) {
        int   ra = __ldg(csr_src + j);
        float na = __ldg(csr_nrm + j);
        const float4* pa = (const float4*)(hw + (size_t)ra * Hdim);
        float4 a0 = pa[lane], a1 = pa[lane + 32];
        acc0.x = fmaf(a0.x, na, acc0.x); acc0.y = fmaf(a0.y, na, acc0.y);
        acc0.z = fmaf(a0.z, na, acc0.z); acc0.w = fmaf(a0.w, na, acc0.w);
        acc1.x = fmaf(a1.x, na, acc1.x); acc1.y = fmaf(a1.y, na, acc1.y);
        acc1.z = fmaf(a1.z, na, acc1.z); acc1.w = fmaf(a1.w, na, acc1.w);
    }

    float4* dst = (float4*)(agg + (size_t)n * Hdim);
    dst[lane]      = acc0;
    dst[lane + 32] = acc1;
}

// ---------------- batchnorm ----------------
__global__ void zero_d_k(double* p, int n) {
    int i = blockIdx.x * blockDim.x + threadIdx.x;
    if (i < n) p[i] = 0.0;
}

__global__ void zero_f_k(float* p, int n) {
    int i = blockIdx.x * blockDim.x + threadIdx.x;
    if (i < n) p[i] = 0.0f;
}

__global__ void bn_stats_k(const float* __restrict__ agg, double* __restrict__ stats, int N) {
    int f = threadIdx.x;            // 256 threads, one feature each
    int chunk = (N + gridDim.x - 1) / gridDim.x;
    int r0 = blockIdx.x * chunk;
    int r1 = min(N, r0 + chunk);
    float s = 0.f, s2 = 0.f;
    for (int r = r0; r < r1; r++) {
        float v = agg[(size_t)r * Hdim + f];
        s += v;
        s2 = fmaf(v, v, s2);
    }
    atomicAdd(&stats[f], (double)s);
    atomicAdd(&stats[Hdim + f], (double)s2);
}

__global__ void bn_final_k(const double* __restrict__ stats,
                           const float* __restrict__ gamma, const float* __restrict__ beta,
                           float* __restrict__ scale, float* __restrict__ shift, int N)
{
    int f = threadIdx.x;
    double mean = stats[f] / N;
    double var = stats[Hdim + f] / N - mean * mean;
    float sc = gamma[f] * rsqrtf((float)var + 1e-5f);
    scale[f] = sc;
    shift[f] = beta[f] - (float)mean * sc;
}

__global__ void bn_apply_k(float* __restrict__ h, const float* __restrict__ scale,
                           const float* __restrict__ shift, int N)
{
    int idx = blockIdx.x * blockDim.x + threadIdx.x;   // over N*64 float4
    if (idx >= N * 64) return;
    int f4 = idx & 63;
    float4 v = ((float4*)h)[idx];
    float4 sc = ((const float4*)scale)[f4];
    float4 sh = ((const float4*)shift)[f4];
    v.x = fmaxf(fmaf(v.x, sc.x, sh.x), 0.f);
    v.y = fmaxf(fmaf(v.y, sc.y, sh.y), 0.f);
    v.z = fmaxf(fmaf(v.z, sc.z, sh.z), 0.f);
    v.w = fmaxf(fmaf(v.w, sc.w, sh.w), 0.f);
    ((float4*)h)[idx] = v;
}

// ---------------- global add pool (batch sorted) ----------------
__global__ void pool_k(const float* __restrict__ h, const int* __restrict__ batch,
                       float* __restrict__ g, int N)
{
    constexpr int CH = 256;
    int f = threadIdx.x;
    int r0 = blockIdx.x * CH;
    int r1 = min(N, r0 + CH);
    if (r0 >= N) return;
    int cur = batch[r0];
    float s = 0.f;
    for (int r = r0; r < r1; r++) {
        int b = batch[r];
        if (b != cur) {
            atomicAdd(&g[cur * Hdim + f], s);
            s = 0.f;
            cur = b;
        }
        s += h[(size_t)r * Hdim + f];
    }
    atomicAdd(&g[cur * Hdim + f], s);
}

// ---------------- MLP head: one block per graph ----------------
__global__ void head_k(const float* __restrict__ g, const float* __restrict__ w1,
                       const float* __restrict__ b1, const float* __restrict__ w2,
                       const float* __restrict__ b2, float* __restrict__ out)
{
    __shared__ float gs[Hdim];
    __shared__ float zs[HD2];
    int b = blockIdx.x;
    int t = threadIdx.x;   // 128 threads
    gs[t]       = g[b * Hdim + t];
    gs[t + 128] = g[b * Hdim + t + 128];
    __syncthreads();
    float acc = b1[t];
    for (int k = 0; k < Hdim; k++) acc = fmaf(gs[k], w1[k * HD2 + t], acc);
    zs[t] = fmaxf(acc, 0.f);
    __syncthreads();
    if (t < OUTdim) {
        float o = b2[t];
        for (int k = 0; k < HD2; k++) o = fmaf(zs[k], w2[k * OUTdim + t], o);
        out[b * OUTdim + t] = o;
    }
}

// ---------------- launch ----------------
extern "C" void kernel_launch(void* const* d_in, const int* in_sizes, int n_in,
                              void* d_out, int out_size)
{
    const float* x       = (const float*)d_in[0];
    const int*   ei      = (const int*)d_in[1];
    const int*   batch   = (const int*)d_in[2];
    const float* node_w  = (const float*)d_in[3];
    const float* node_b  = (const float*)d_in[4];
    const float* conv_w  = (const float*)d_in[5];
    const float* conv_b  = (const float*)d_in[6];
    const float* bn_g    = (const float*)d_in[7];
    const float* bn_b    = (const float*)d_in[8];
    const float* head_w1 = (const float*)d_in[9];
    const float* head_b1 = (const float*)d_in[10];
    const float* head_w2 = (const float*)d_in[11];
    const float* head_b2 = (const float*)d_in[12];
    float* out = (float*)d_out;

    int N = in_sizes[0] / INdim;
    int E = in_sizes[1] / 2;
    const int* rowi = ei;
    const int* coli = ei + E;

    float *bufA, *bufB, *dis, *scale, *shift, *pool, *csr_nrm;
    int *cnt, *rowptr, *cursor, *partial, *bsum, *csr_src;
    double* stats;
    cudaGetSymbolAddress((void**)&bufA, g_bufA);
    cudaGetSymbolAddress((void**)&bufB, g_bufB);
    cudaGetSymbolAddress((void**)&dis, g_dis);
    cudaGetSymbolAddress((void**)&cnt, g_cnt);
    cudaGetSymbolAddress((void**)&rowptr, g_rowptr);
    cudaGetSymbolAddress((void**)&cursor, g_cursor);
    cudaGetSymbolAddress((void**)&partial, g_partial);
    cudaGetSymbolAddress((void**)&bsum, g_bsum);
    cudaGetSymbolAddress((void**)&csr_src, g_csr_src);
    cudaGetSymbolAddress((void**)&csr_nrm, g_csr_nrm);
    cudaGetSymbolAddress((void**)&stats, g_stats);
    cudaGetSymbolAddress((void**)&scale, g_scale);
    cudaGetSymbolAddress((void**)&shift, g_shift);
    cudaGetSymbolAddress((void**)&pool, g_pool);

    // ---- CSR build (once per call) ----
    int nblk1 = (N + SCAN_B - 1) / SCAN_B;
    zero_i_k<<<(N + 255) / 256, 256>>>(cnt, N);
    count_k<<<592, 256>>>(coli, cnt, E);
    scan1_k<<<nblk1, SCAN_B>>>(cnt, partial, bsum, N);
    scan2_k<<<1, SCAN_B>>>(bsum, nblk1);
    scan3_k<<<(N + 255) / 256, 256>>>(partial, bsum, cnt, rowptr, cursor, dis, N, E);
    fill_k<<<592, 256>>>(rowi, coli, dis, cursor, csr_src, csr_nrm, E);

    dim3 ggrid(2, (N + 127) / 128);

    // node embedding: h = x @ node_w + node_b  -> bufA
    gemm_k<<<ggrid, 256>>>(x, node_w, node_b, bufA, N, INdim);

    int nElem4 = N * (Hdim / 4);
    int aggBlocks = (N + 7) / 8;       // 8 warps per block, warp per node
    for (int l = 0; l < NLAY; l++) {
        // hw = h @ conv_w[l] -> bufB
        gemm_k<<<ggrid, 256>>>(bufA, conv_w + (size_t)l * Hdim * Hdim, nullptr, bufB, N, Hdim);
        // gather aggregation (self-loop + bias fused) -> bufA
        aggregate_k<<<aggBlocks, 256>>>(bufB, bufA, rowptr, csr_src, csr_nrm, dis,
                                        conv_b + l * Hdim, N);
        // batchnorm + relu in place
        zero_d_k<<<2, 256>>>(stats, 2 * Hdim);
        bn_stats_k<<<200, 256>>>(bufA, stats, N);
        bn_final_k<<<1, 256>>>(stats, bn_g + l * Hdim, bn_b + l * Hdim, scale, shift, N);
        bn_apply_k<<<(nElem4 + 255) / 256, 256>>>(bufA, scale, shift, N);
    }

    // global add pool + head
    zero_f_k<<<(NGRAPH * Hdim + 255) / 256, 256>>>(pool, NGRAPH * Hdim);
    pool_k<<<(N + 255) / 256, 256>>>(bufA, batch, pool, N);
    head_k<<<NGRAPH, HD2>>>(pool, head_w1, head_b1, head_w2, head_b2, out);
}

// round 4
// speedup vs baseline: 1.2326x; 1.0095x over previous
#include <cuda_runtime.h>
#include <math.h>

// ---------------- problem constants ----------------
constexpr int Hdim   = 256;
constexpr int INdim  = 64;
constexpr int HD2    = 128;
constexpr int OUTdim = 12;
constexpr int NLAY   = 3;
constexpr int NGRAPH = 64;
constexpr int NMAX   = 50000;
constexpr int EMAX   = 600000;
constexpr int SCAN_B = 512;
constexpr int MAXBLK1 = (NMAX + SCAN_B - 1) / SCAN_B;

// ---------------- scratch (device globals, no allocation) ----------------
__device__ float  g_bufA[(size_t)NMAX * Hdim];   // h / agg
__device__ float  g_bufB[(size_t)NMAX * Hdim];   // hw
__device__ float  g_dis[NMAX];                   // rsqrt(deg)
__device__ int    g_cnt[NMAX];
__device__ int    g_rowptr[NMAX + 1];
__device__ int    g_cursor[NMAX];
__device__ int    g_partial[NMAX];
__device__ int    g_bsum[MAXBLK1 + 1];
__device__ int    g_csr_src[EMAX];
__device__ float  g_csr_nrm[EMAX];
__device__ double g_stats[NLAY * 2 * Hdim];      // per-layer sum, sumsq
__device__ float  g_scale[NLAY * Hdim];
__device__ float  g_shift[NLAY * Hdim];
__device__ float  g_pool[NGRAPH * Hdim];

// ---------------- one-shot zeroing ----------------
__global__ void zero_all_k(int* cnt, double* stats, float* pool, int N) {
    int i = blockIdx.x * blockDim.x + threadIdx.x;
    if (i < N) cnt[i] = 0;
    if (i < NLAY * 2 * Hdim) stats[i] = 0.0;
    if (i < NGRAPH * Hdim) pool[i] = 0.0f;
}

// ---------------- CSR build ----------------
__global__ void count_k(const int* __restrict__ coli, int* __restrict__ cnt, int E) {
    int i = blockIdx.x * blockDim.x + threadIdx.x;
    int stride = gridDim.x * blockDim.x;
    for (int e = i; e < E; e += stride) atomicAdd(&cnt[coli[e]], 1);
}

__global__ void scan1_k(const int* __restrict__ cnt, int* __restrict__ partial,
                        int* __restrict__ bsum, int N)
{
    __shared__ int sh[SCAN_B];
    int t = threadIdx.x;
    int i = blockIdx.x * SCAN_B + t;
    int v = (i < N) ? cnt[i] : 0;
    sh[t] = v;
    __syncthreads();
#pragma unroll
    for (int off = 1; off < SCAN_B; off <<= 1) {
        int add = (t >= off) ? sh[t - off] : 0;
        __syncthreads();
        sh[t] += add;
        __syncthreads();
    }
    if (i < N) partial[i] = sh[t] - v;
    if (t == SCAN_B - 1) bsum[blockIdx.x] = sh[t];
}

__global__ void scan2_k(int* __restrict__ bsum, int nb) {
    __shared__ int sh[SCAN_B];
    int t = threadIdx.x;
    int v = (t < nb) ? bsum[t] : 0;
    sh[t] = v;
    __syncthreads();
#pragma unroll
    for (int off = 1; off < SCAN_B; off <<= 1) {
        int add = (t >= off) ? sh[t - off] : 0;
        __syncthreads();
        sh[t] += add;
        __syncthreads();
    }
    if (t < nb) bsum[t] = sh[t] - v;
}

__global__ void scan3_k(const int* __restrict__ partial, const int* __restrict__ bsum,
                        const int* __restrict__ cnt, int* __restrict__ rowptr,
                        int* __restrict__ cursor, float* __restrict__ dis, int N, int E)
{
    int i = blockIdx.x * blockDim.x + threadIdx.x;
    if (i < N) {
        int rp = partial[i] + bsum[i / SCAN_B];
        rowptr[i] = rp;
        cursor[i] = rp;
        dis[i] = rsqrtf((float)(cnt[i] + 1));
    }
    if (i == 0) rowptr[N] = E;
}

__global__ void fill_k(const int* __restrict__ rowi, const int* __restrict__ coli,
                       const float* __restrict__ dis, int* __restrict__ cursor,
                       int* __restrict__ csr_src, float* __restrict__ csr_nrm, int E)
{
    int i = blockIdx.x * blockDim.x + threadIdx.x;
    int stride = gridDim.x * blockDim.x;
    for (int e = i; e < E; e += stride) {
        int r = rowi[e], c = coli[e];
        int slot = atomicAdd(&cursor[c], 1);
        csr_src[slot] = r;
        csr_nrm[slot] = dis[r] * dis[c];
    }
}

// ---------------- SGEMM with software pipeline + fused input affine/ReLU -------
// C[M,256] = f(A)[M,K] @ B[K,256] (+bias);  f(a)=relu(a*scale[k]+shift[k]) if scale
__global__ __launch_bounds__(256, 2)
void gemm_k(const float* __restrict__ A, const float* __restrict__ B,
            const float* __restrict__ bias, float* __restrict__ C,
            const float* __restrict__ scale, const float* __restrict__ shift,
            int M, int K)
{
    constexpr int BM = 128, BN = 128, BK = 8;
    __shared__ float As[BK][BM];
    __shared__ float Bs[BK][BN];

    int tid = threadIdx.x;
    int cx = tid % 16;
    int ry = tid / 16;
    int rowBase = blockIdx.y * BM;
    int colBase = blockIdx.x * BN;

    float acc[8][8];
#pragma unroll
    for (int i = 0; i < 8; i++)
#pragma unroll
        for (int j = 0; j < 8; j++) acc[i][j] = 0.0f;

    int aRow = tid >> 1;
    int aCol = (tid & 1) * 4;
    int bRow = tid >> 5;
    int bCol = (tid & 31) * 4;

    bool aValid = (rowBase + aRow) < M;
    const float* Aptr = A + (size_t)(rowBase + aRow) * K + aCol;
    const float* Bptr = B + (size_t)bRow * 256 + colBase + bCol;

    auto loadA = [&](int kk) -> float4 {
        float4 v = aValid ? *(const float4*)(Aptr + kk) : make_float4(0.f, 0.f, 0.f, 0.f);
        if (scale) {
            float4 sc = *(const float4*)(scale + kk + aCol);
            float4 sh = *(const float4*)(shift + kk + aCol);
            v.x = fmaxf(fmaf(v.x, sc.x, sh.x), 0.f);
            v.y = fmaxf(fmaf(v.y, sc.y, sh.y), 0.f);
            v.z = fmaxf(fmaf(v.z, sc.z, sh.z), 0.f);
            v.w = fmaxf(fmaf(v.w, sc.w, sh.w), 0.f);
        }
        return v;
    };

    float4 av = loadA(0);
    float4 bv = *(const float4*)(Bptr);

    for (int k0 = 0; k0 < K; k0 += BK) {
        __syncthreads();
        As[aCol + 0][aRow] = av.x;
        As[aCol + 1][aRow] = av.y;
        As[aCol + 2][aRow] = av.z;
        As[aCol + 3][aRow] = av.w;
        *(float4*)&Bs[bRow][bCol] = bv;
        __syncthreads();
        if (k0 + BK < K) {                       // prefetch next tile
            av = loadA(k0 + BK);
            bv = *(const float4*)(Bptr + (size_t)(k0 + BK) * 256);
        }
#pragma unroll
        for (int k = 0; k < BK; k++) {
            float a[8], b[8];
#pragma unroll
            for (int i = 0; i < 8; i++) a[i] = As[k][ry * 8 + i];
#pragma unroll
            for (int j = 0; j < 8; j++) b[j] = Bs[k][cx * 8 + j];
#pragma unroll
            for (int i = 0; i < 8; i++)
#pragma unroll
                for (int j = 0; j < 8; j++) acc[i][j] = fmaf(a[i], b[j], acc[i][j]);
        }
    }

#pragma unroll
    for (int i = 0; i < 8; i++) {
        int r = rowBase + ry * 8 + i;
        if (r < M) {
#pragma unroll
            for (int j = 0; j < 8; j += 4) {
                int c = colBase + cx * 8 + j;
                float4 v;
                v.x = acc[i][j];     v.y = acc[i][j + 1];
                v.z = acc[i][j + 2]; v.w = acc[i][j + 3];
                if (bias) {
                    v.x += bias[c];     v.y += bias[c + 1];
                    v.z += bias[c + 2]; v.w += bias[c + 3];
                }
                *(float4*)&C[(size_t)r * 256 + c] = v;
            }
        }
    }
}

// ---------------- aggregate: warp/node CSR gather + fused BN statistics ---------
__device__ __forceinline__ void fma4(float4& a, const float4& v, float s) {
    a.x = fmaf(v.x, s, a.x); a.y = fmaf(v.y, s, a.y);
    a.z = fmaf(v.z, s, a.z); a.w = fmaf(v.w, s, a.w);
}

__global__ __launch_bounds__(256)
void aggregate_k(const float* __restrict__ hw, float* __restrict__ agg,
                 const int* __restrict__ rowptr, const int* __restrict__ csr_src,
                 const float* __restrict__ csr_nrm, const float* __restrict__ dis,
                 const float* __restrict__ convb, double* __restrict__ stats, int N)
{
    __shared__ float4 sh_s[8][64];   // per-warp partial sums
    __shared__ float4 sh_q[8][64];   // per-warp partial sumsq

    int tid = threadIdx.x;
    int wid = tid >> 5;
    int lane = tid & 31;

    float4 b0 = ((const float4*)convb)[lane];
    float4 b1 = ((const float4*)convb)[lane + 32];

    float4 tsum0 = make_float4(0, 0, 0, 0), tsum1 = make_float4(0, 0, 0, 0);
    float4 tsq0  = make_float4(0, 0, 0, 0), tsq1  = make_float4(0, 0, 0, 0);

    for (int n = blockIdx.x * 8 + wid; n < N; n += gridDim.x * 8) {
        float dn = __ldg(dis + n);
        float sn = dn * dn;
        const float4* self = (const float4*)(hw + (size_t)n * Hdim);
        float4 acc0 = b0, acc1 = b1;
        fma4(acc0, self[lane], sn);
        fma4(acc1, self[lane + 32], sn);

        int j  = __ldg(rowptr + n);
        int e1 = __ldg(rowptr + n + 1);

        for (; j + 3 < e1; j += 4) {
            int   r0 = __ldg(csr_src + j),     r1 = __ldg(csr_src + j + 1);
            int   r2 = __ldg(csr_src + j + 2), r3 = __ldg(csr_src + j + 3);
            float n0 = __ldg(csr_nrm + j),     n1 = __ldg(csr_nrm + j + 1);
            float n2 = __ldg(csr_nrm + j + 2), n3 = __ldg(csr_nrm + j + 3);
            const float4* p0 = (const float4*)(hw + (size_t)r0 * Hdim);
            const float4* p1 = (const float4*)(hw + (size_t)r1 * Hdim);
            const float4* p2 = (const float4*)(hw + (size_t)r2 * Hdim);
            const float4* p3 = (const float4*)(hw + (size_t)r3 * Hdim);
            float4 a0 = p0[lane], a1 = p0[lane + 32];
            float4 c0 = p1[lane], c1 = p1[lane + 32];
            float4 d0 = p2[lane], d1 = p2[lane + 32];
            float4 e0 = p3[lane], e4 = p3[lane + 32];
            fma4(acc0, a0, n0); fma4(acc1, a1, n0);
            fma4(acc0, c0, n1); fma4(acc1, c1, n1);
            fma4(acc0, d0, n2); fma4(acc1, d1, n2);
            fma4(acc0, e0, n3); fma4(acc1, e4, n3);
        }
        for (; j < e1; j++) {
            int   r = __ldg(csr_src + j);
            float nn = __ldg(csr_nrm + j);
            const float4* p = (const float4*)(hw + (size_t)r * Hdim);
            fma4(acc0, p[lane], nn);
            fma4(acc1, p[lane + 32], nn);
        }

        float4* dst = (float4*)(agg + (size_t)n * Hdim);
        dst[lane]      = acc0;
        dst[lane + 32] = acc1;

        // stats accumulation in registers
        tsum0.x += acc0.x; tsum0.y += acc0.y; tsum0.z += acc0.z; tsum0.w += acc0.w;
        tsum1.x += acc1.x; tsum1.y += acc1.y; tsum1.z += acc1.z; tsum1.w += acc1.w;
        tsq0.x = fmaf(acc0.x, acc0.x, tsq0.x); tsq0.y = fmaf(acc0.y, acc0.y, tsq0.y);
        tsq0.z = fmaf(acc0.z, acc0.z, tsq0.z); tsq0.w = fmaf(acc0.w, acc0.w, tsq0.w);
        tsq1.x = fmaf(acc1.x, acc1.x, tsq1.x); tsq1.y = fmaf(acc1.y, acc1.y, tsq1.y);
        tsq1.z = fmaf(acc1.z, acc1.z, tsq1.z); tsq1.w = fmaf(acc1.w, acc1.w, tsq1.w);
    }

    // cross-warp reduce: feature layout  [lane]=f/4 for feats lane*4.., [lane+32] for 128+lane*4..
    sh_s[wid][lane]      = tsum0;  sh_s[wid][lane + 32] = tsum1;
    sh_q[wid][lane]      = tsq0;   sh_q[wid][lane + 32] = tsq1;
    __syncthreads();

    // 256 threads: thread t reduces feature t over 8 warps
    const float* ps = (const float*)sh_s;
    const float* pq = (const float*)sh_q;
    float s = 0.f, q = 0.f;
#pragma unroll
    for (int w = 0; w < 8; w++) {
        s += ps[w * 256 + tid];
        q += pq[w * 256 + tid];
    }
    atomicAdd(&stats[tid], (double)s);
    atomicAdd(&stats[Hdim + tid], (double)q);
}

// ---------------- bn scale/shift ----------------
__global__ void bn_final_k(const double* __restrict__ stats,
                           const float* __restrict__ gamma, const float* __restrict__ beta,
                           float* __restrict__ scale, float* __restrict__ shift, int N)
{
    int f = threadIdx.x;
    double mean = stats[f] / N;
    double var = stats[Hdim + f] / N - mean * mean;
    float sc = gamma[f] * rsqrtf((float)var + 1e-5f);
    scale[f] = sc;
    shift[f] = beta[f] - (float)mean * sc;
}

// ---------------- global add pool with fused BN affine + ReLU ----------------
__global__ void pool_k(const float* __restrict__ h, const int* __restrict__ batch,
                       const float* __restrict__ scale, const float* __restrict__ shift,
                       float* __restrict__ g, int N)
{
    constexpr int CH = 256;
    int f = threadIdx.x;
    int r0 = blockIdx.x * CH;
    int r1 = min(N, r0 + CH);
    if (r0 >= N) return;
    float sc = scale[f], sh = shift[f];
    int cur = batch[r0];
    float s = 0.f;
    for (int r = r0; r < r1; r++) {
        int b = batch[r];
        if (b != cur) {
            atomicAdd(&g[cur * Hdim + f], s);
            s = 0.f;
            cur = b;
        }
        s += fmaxf(fmaf(h[(size_t)r * Hdim + f], sc, sh), 0.f);
    }
    atomicAdd(&g[cur * Hdim + f], s);
}

// ---------------- MLP head ----------------
__global__ void head_k(const float* __restrict__ g, const float* __restrict__ w1,
                       const float* __restrict__ b1, const float* __restrict__ w2,
                       const float* __restrict__ b2, float* __restrict__ out)
{
    __shared__ float gs[Hdim];
    __shared__ float zs[HD2];
    int b = blockIdx.x;
    int t = threadIdx.x;
    gs[t]       = g[b * Hdim + t];
    gs[t + 128] = g[b * Hdim + t + 128];
    __syncthreads();
    float acc = b1[t];
    for (int k = 0; k < Hdim; k++) acc = fmaf(gs[k], w1[k * HD2 + t], acc);
    zs[t] = fmaxf(acc, 0.f);
    __syncthreads();
    if (t < OUTdim) {
        float o = b2[t];
        for (int k = 0; k < HD2; k++) o = fmaf(zs[k], w2[k * OUTdim + t], o);
        out[b * OUTdim + t] = o;
    }
}

// ---------------- launch ----------------
extern "C" void kernel_launch(void* const* d_in, const int* in_sizes, int n_in,
                              void* d_out, int out_size)
{
    const float* x       = (const float*)d_in[0];
    const int*   ei      = (const int*)d_in[1];
    const int*   batch   = (const int*)d_in[2];
    const float* node_w  = (const float*)d_in[3];
    const float* node_b  = (const float*)d_in[4];
    const float* conv_w  = (const float*)d_in[5];
    const float* conv_b  = (const float*)d_in[6];
    const float* bn_g    = (const float*)d_in[7];
    const float* bn_b    = (const float*)d_in[8];
    const float* head_w1 = (const float*)d_in[9];
    const float* head_b1 = (const float*)d_in[10];
    const float* head_w2 = (const float*)d_in[11];
    const float* head_b2 = (const float*)d_in[12];
    float* out = (float*)d_out;

    int N = in_sizes[0] / INdim;
    int E = in_sizes[1] / 2;
    const int* rowi = ei;
    const int* coli = ei + E;

    float *bufA, *bufB, *dis, *scale, *shift, *pool, *csr_nrm;
    int *cnt, *rowptr, *cursor, *partial, *bsum, *csr_src;
    double* stats;
    cudaGetSymbolAddress((void**)&bufA, g_bufA);
    cudaGetSymbolAddress((void**)&bufB, g_bufB);
    cudaGetSymbolAddress((void**)&dis, g_dis);
    cudaGetSymbolAddress((void**)&cnt, g_cnt);
    cudaGetSymbolAddress((void**)&rowptr, g_rowptr);
    cudaGetSymbolAddress((void**)&cursor, g_cursor);
    cudaGetSymbolAddress((void**)&partial, g_partial);
    cudaGetSymbolAddress((void**)&bsum, g_bsum);
    cudaGetSymbolAddress((void**)&csr_src, g_csr_src);
    cudaGetSymbolAddress((void**)&csr_nrm, g_csr_nrm);
    cudaGetSymbolAddress((void**)&stats, g_stats);
    cudaGetSymbolAddress((void**)&scale, g_scale);
    cudaGetSymbolAddress((void**)&shift, g_shift);
    cudaGetSymbolAddress((void**)&pool, g_pool);

    // ---- zero + CSR build ----
    int nblk1 = (N + SCAN_B - 1) / SCAN_B;
    zero_all_k<<<(N + 255) / 256, 256>>>(cnt, stats, pool, N);
    count_k<<<592, 256>>>(coli, cnt, E);
    scan1_k<<<nblk1, SCAN_B>>>(cnt, partial, bsum, N);
    scan2_k<<<1, SCAN_B>>>(bsum, nblk1);
    scan3_k<<<(N + 255) / 256, 256>>>(partial, bsum, cnt, rowptr, cursor, dis, N, E);
    fill_k<<<592, 256>>>(rowi, coli, dis, cursor, csr_src, csr_nrm, E);

    dim3 ggrid(2, (N + 127) / 128);

    // node embedding: h0 = x @ node_w + node_b  -> bufA   (no input affine)
    gemm_k<<<ggrid, 256>>>(x, node_w, node_b, bufA, nullptr, nullptr, N, INdim);

    int aggBlocks = 1184;            // persistent-ish: 8 blocks/SM
    for (int l = 0; l < NLAY; l++) {
        const float* sc = (l == 0) ? nullptr : scale + (l - 1) * Hdim;
        const float* sh = (l == 0) ? nullptr : shift + (l - 1) * Hdim;
        // hw = f(h) @ conv_w[l] -> bufB   (f = BN affine + relu of previous layer)
        gemm_k<<<ggrid, 256>>>(bufA, conv_w + (size_t)l * Hdim * Hdim, nullptr, bufB,
                               sc, sh, N, Hdim);
        // gather aggregation + fused BN stats -> bufA (pre-BN)
        aggregate_k<<<aggBlocks, 256>>>(bufB, bufA, rowptr, csr_src, csr_nrm, dis,
                                        conv_b + l * Hdim, stats + l * 2 * Hdim, N);
        bn_final_k<<<1, 256>>>(stats + l * 2 * Hdim, bn_g + l * Hdim, bn_b + l * Hdim,
                               scale + l * Hdim, shift + l * Hdim, N);
    }

    // pool (applies layer-2 BN affine + relu) + head
    pool_k<<<(N + 255) / 256, 256>>>(bufA, batch, scale + 2 * Hdim, shift + 2 * Hdim,
                                     pool, N);
    head_k<<<NGRAPH, HD2>>>(pool, head_w1, head_b1, head_w2, head_b2, out);
}

// round 7
// speedup vs baseline: 1.2326x; 1.0000x over previous
#include <cuda_runtime.h>
#include <math.h>

// ---------------- problem constants ----------------
constexpr int Hdim   = 256;
constexpr int INdim  = 64;
constexpr int HD2    = 128;
constexpr int OUTdim = 12;
constexpr int NLAY   = 3;
constexpr int NGRAPH = 64;
constexpr int NMAX   = 50000;
constexpr int EMAX   = 600000;
constexpr int SCAN_B = 512;
constexpr int MAXBLK1 = (NMAX + SCAN_B - 1) / SCAN_B;

// ---------------- scratch (device globals, no allocation) ----------------
__device__ float  g_bufA[(size_t)NMAX * Hdim];
__device__ float  g_bufB[(size_t)NMAX * Hdim];
__device__ float  g_dis[NMAX];
__device__ int    g_cnt[NMAX];
__device__ int    g_rowptr[NMAX + 1];
__device__ int    g_cursor[NMAX];
__device__ int    g_partial[NMAX];
__device__ int    g_bsum[MAXBLK1 + 1];
__device__ int2   g_csr[EMAX];                   // (src, nrm bits)
__device__ double g_stats[NLAY * 2 * Hdim];
__device__ float  g_scale[NLAY * Hdim];
__device__ float  g_shift[NLAY * Hdim];
__device__ float  g_pool[NGRAPH * Hdim];

// ---------------- one-shot zeroing ----------------
__global__ void zero_all_k(int* cnt, double* stats, float* pool, int N) {
    int i = blockIdx.x * blockDim.x + threadIdx.x;
    if (i < N) cnt[i] = 0;
    if (i < NLAY * 2 * Hdim) stats[i] = 0.0;
    if (i < NGRAPH * Hdim) pool[i] = 0.0f;
}

// ---------------- CSR build ----------------
__global__ void count_k(const int* __restrict__ coli, int* __restrict__ cnt, int E) {
    int i = blockIdx.x * blockDim.x + threadIdx.x;
    int stride = gridDim.x * blockDim.x;
    for (int e = i; e < E; e += stride) atomicAdd(&cnt[coli[e]], 1);
}

__global__ void scan1_k(const int* __restrict__ cnt, int* __restrict__ partial,
                        int* __restrict__ bsum, int N)
{
    __shared__ int sh[SCAN_B];
    int t = threadIdx.x;
    int i = blockIdx.x * SCAN_B + t;
    int v = (i < N) ? cnt[i] : 0;
    sh[t] = v;
    __syncthreads();
#pragma unroll
    for (int off = 1; off < SCAN_B; off <<= 1) {
        int add = (t >= off) ? sh[t - off] : 0;
        __syncthreads();
        sh[t] += add;
        __syncthreads();
    }
    if (i < N) partial[i] = sh[t] - v;
    if (t == SCAN_B - 1) bsum[blockIdx.x] = sh[t];
}

__global__ void scan2_k(int* __restrict__ bsum, int nb) {
    __shared__ int sh[SCAN_B];
    int t = threadIdx.x;
    int v = (t < nb) ? bsum[t] : 0;
    sh[t] = v;
    __syncthreads();
#pragma unroll
    for (int off = 1; off < SCAN_B; off <<= 1) {
        int add = (t >= off) ? sh[t - off] : 0;
        __syncthreads();
        sh[t] += add;
        __syncthreads();
    }
    if (t < nb) bsum[t] = sh[t] - v;
}

__global__ void scan3_k(const int* __restrict__ partial, const int* __restrict__ bsum,
                        const int* __restrict__ cnt, int* __restrict__ rowptr,
                        int* __restrict__ cursor, float* __restrict__ dis, int N, int E)
{
    int i = blockIdx.x * blockDim.x + threadIdx.x;
    if (i < N) {
        int rp = partial[i] + bsum[i / SCAN_B];
        rowptr[i] = rp;
        cursor[i] = rp;
        dis[i] = rsqrtf((float)(cnt[i] + 1));
    }
    if (i == 0) rowptr[N] = E;
}

__global__ void fill_k(const int* __restrict__ rowi, const int* __restrict__ coli,
                       const float* __restrict__ dis, int* __restrict__ cursor,
                       int2* __restrict__ csr, int E)
{
    int i = blockIdx.x * blockDim.x + threadIdx.x;
    int stride = gridDim.x * blockDim.x;
    for (int e = i; e < E; e += stride) {
        int r = rowi[e], c = coli[e];
        int slot = atomicAdd(&cursor[c], 1);
        csr[slot] = make_int2(r, __float_as_int(dis[r] * dis[c]));
    }
}

// ---------------- SGEMM: double-buffered smem, 1 sync/tile --------------------
// C[M,256] = f(A)[M,K] @ B[K,256] (+bias);  f(a)=relu(a*scale[k]+shift[k]) if scale
__global__ __launch_bounds__(256, 2)
void gemm_k(const float* __restrict__ A, const float* __restrict__ B,
            const float* __restrict__ bias, float* __restrict__ C,
            const float* __restrict__ scale, const float* __restrict__ shift,
            int M, int K)
{
    constexpr int BM = 128, BN = 128, BK = 8;
    __shared__ float As[2][BK][BM];
    __shared__ float Bs[2][BK][BN];

    int tid = threadIdx.x;
    int cx = tid % 16;
    int ry = tid / 16;
    int rowBase = blockIdx.y * BM;
    int colBase = blockIdx.x * BN;

    float acc[8][8];
#pragma unroll
    for (int i = 0; i < 8; i++)
#pragma unroll
        for (int j = 0; j < 8; j++) acc[i][j] = 0.0f;

    int aRow = tid >> 1;
    int aCol = (tid & 1) * 4;
    int bRow = tid >> 5;
    int bCol = (tid & 31) * 4;

    bool aValid = (rowBase + aRow) < M;
    const float* Aptr = A + (size_t)(rowBase + aRow) * K + aCol;
    const float* Bptr = B + (size_t)bRow * 256 + colBase + bCol;

    auto loadA = [&](int kk) -> float4 {
        float4 v = aValid ? *(const float4*)(Aptr + kk) : make_float4(0.f, 0.f, 0.f, 0.f);
        if (scale) {
            float4 sc = *(const float4*)(scale + kk + aCol);
            float4 sh = *(const float4*)(shift + kk + aCol);
            v.x = fmaxf(fmaf(v.x, sc.x, sh.x), 0.f);
            v.y = fmaxf(fmaf(v.y, sc.y, sh.y), 0.f);
            v.z = fmaxf(fmaf(v.z, sc.z, sh.z), 0.f);
            v.w = fmaxf(fmaf(v.w, sc.w, sh.w), 0.f);
        }
        return v;
    };

    // prologue: tile 0 -> buf 0
    {
        float4 av = loadA(0);
        float4 bv = *(const float4*)(Bptr);
        As[0][aCol + 0][aRow] = av.x;
        As[0][aCol + 1][aRow] = av.y;
        As[0][aCol + 2][aRow] = av.z;
        As[0][aCol + 3][aRow] = av.w;
        *(float4*)&Bs[0][bRow][bCol] = bv;
    }
    __syncthreads();

    int nTiles = K / BK;
    for (int t = 0; t < nTiles; t++) {
        int buf = t & 1;
        float4 av, bv;
        bool more = (t + 1) < nTiles;
        if (more) {                       // issue next-tile global loads first
            av = loadA((t + 1) * BK);
            bv = *(const float4*)(Bptr + (size_t)(t + 1) * BK * 256);
        }
#pragma unroll
        for (int k = 0; k < BK; k++) {
            float a[8], b[8];
#pragma unroll
            for (int i = 0; i < 8; i++) a[i] = As[buf][k][ry * 8 + i];
#pragma unroll
            for (int j = 0; j < 8; j++) b[j] = Bs[buf][k][cx * 8 + j];
#pragma unroll
            for (int i = 0; i < 8; i++)
#pragma unroll
                for (int j = 0; j < 8; j++) acc[i][j] = fmaf(a[i], b[j], acc[i][j]);
        }
        if (more) {
            As[buf ^ 1][aCol + 0][aRow] = av.x;
            As[buf ^ 1][aCol + 1][aRow] = av.y;
            As[buf ^ 1][aCol + 2][aRow] = av.z;
            As[buf ^ 1][aCol + 3][aRow] = av.w;
            *(float4*)&Bs[buf ^ 1][bRow][bCol] = bv;
        }
        __syncthreads();
    }

#pragma unroll
    for (int i = 0; i < 8; i++) {
        int r = rowBase + ry * 8 + i;
        if (r < M) {
#pragma unroll
            for (int j = 0; j < 8; j += 4) {
                int c = colBase + cx * 8 + j;
                float4 v;
                v.x = acc[i][j];     v.y = acc[i][j + 1];
                v.z = acc[i][j + 2]; v.w = acc[i][j + 3];
                if (bias) {
                    v.x += bias[c];     v.y += bias[c + 1];
                    v.z += bias[c + 2]; v.w += bias[c + 3];
                }
                *(float4*)&C[(size_t)r * 256 + c] = v;
            }
        }
    }
}

// ---------------- aggregate v2: 2 warps/node, packed csr, fused BN stats -------
__device__ __forceinline__ void fma4(float4& a, const float4& v, float s) {
    a.x = fmaf(v.x, s, a.x); a.y = fmaf(v.y, s, a.y);
    a.z = fmaf(v.z, s, a.z); a.w = fmaf(v.w, s, a.w);
}

__global__ __launch_bounds__(256)
void aggregate_k(const float* __restrict__ hw, float* __restrict__ agg,
                 const int* __restrict__ rowptr, const int2* __restrict__ csr,
                 const float* __restrict__ dis,
                 const float* __restrict__ convb, double* __restrict__ stats, int N)
{
    __shared__ float4 sh_s[8][32];
    __shared__ float4 sh_q[8][32];

    int tid = threadIdx.x;
    int wid = tid >> 5;
    int lane = tid & 31;

    int gw = blockIdx.x * 8 + wid;       // global warp
    int half = gw & 1;                   // feature half (parity preserved: stride even)
    int rowOff = half * 32 + lane;       // float4 index within a 256-f row

    float4 bseg = ((const float4*)convb)[rowOff];
    float4 tsum = make_float4(0, 0, 0, 0);
    float4 tsq  = make_float4(0, 0, 0, 0);

    int nodeStride = gridDim.x * 4;      // (gridDim.x*8 warps) / 2

    for (int n = gw >> 1; n < N; n += nodeStride) {
        float dn = __ldg(dis + n);
        float sn = dn * dn;
        float4 acc = bseg;
        fma4(acc, ((const float4*)(hw + (size_t)n * Hdim))[rowOff], sn);

        int j  = __ldg(rowptr + n);
        int e1 = __ldg(rowptr + n + 1);

        for (; j + 3 < e1; j += 4) {
            int2 p0 = __ldg(csr + j);
            int2 p1 = __ldg(csr + j + 1);
            int2 p2 = __ldg(csr + j + 2);
            int2 p3 = __ldg(csr + j + 3);
            float4 v0 = ((const float4*)(hw + (size_t)p0.x * Hdim))[rowOff];
            float4 v1 = ((const float4*)(hw + (size_t)p1.x * Hdim))[rowOff];
            float4 v2 = ((const float4*)(hw + (size_t)p2.x * Hdim))[rowOff];
            float4 v3 = ((const float4*)(hw + (size_t)p3.x * Hdim))[rowOff];
            fma4(acc, v0, __int_as_float(p0.y));
            fma4(acc, v1, __int_as_float(p1.y));
            fma4(acc, v2, __int_as_float(p2.y));
            fma4(acc, v3, __int_as_float(p3.y));
        }
        for (; j < e1; j++) {
            int2 p = __ldg(csr + j);
            float4 v = ((const float4*)(hw + (size_t)p.x * Hdim))[rowOff];
            fma4(acc, v, __int_as_float(p.y));
        }

        ((float4*)(agg + (size_t)n * Hdim))[rowOff] = acc;

        tsum.x += acc.x; tsum.y += acc.y; tsum.z += acc.z; tsum.w += acc.w;
        tsq.x = fmaf(acc.x, acc.x, tsq.x); tsq.y = fmaf(acc.y, acc.y, tsq.y);
        tsq.z = fmaf(acc.z, acc.z, tsq.z); tsq.w = fmaf(acc.w, acc.w, tsq.w);
    }

    sh_s[wid][lane] = tsum;
    sh_q[wid][lane] = tsq;
    __syncthreads();

    // thread t reduces scalar feature t over the 4 warps holding its half
    int f = tid;
    int f4 = f >> 2, comp = f & 3;
    int hf = f4 >> 5, l = f4 & 31;
    float s = 0.f, q = 0.f;
#pragma unroll
    for (int k = 0; k < 4; k++) {
        int w = hf + 2 * k;
        s += ((const float*)&sh_s[w][l])[comp];
        q += ((const float*)&sh_q[w][l])[comp];
    }
    atomicAdd(&stats[f], (double)s);
    atomicAdd(&stats[Hdim + f], (double)q);
}

// ---------------- bn scale/shift ----------------
__global__ void bn_final_k(const double* __restrict__ stats,
                           const float* __restrict__ gamma, const float* __restrict__ beta,
                           float* __restrict__ scale, float* __restrict__ shift, int N)
{
    int f = threadIdx.x;
    double mean = stats[f] / N;
    double var = stats[Hdim + f] / N - mean * mean;
    float sc = gamma[f] * rsqrtf((float)var + 1e-5f);
    scale[f] = sc;
    shift[f] = beta[f] - (float)mean * sc;
}

// ---------------- global add pool with fused BN affine + ReLU ----------------
__global__ void pool_k(const float* __restrict__ h, const int* __restrict__ batch,
                       const float* __restrict__ scale, const float* __restrict__ shift,
                       float* __restrict__ g, int N)
{
    constexpr int CH = 256;
    int f = threadIdx.x;
    int r0 = blockIdx.x * CH;
    int r1 = min(N, r0 + CH);
    if (r0 >= N) return;
    float sc = scale[f], sh = shift[f];
    int cur = batch[r0];
    float s = 0.f;
    for (int r = r0; r < r1; r++) {
        int b = batch[r];
        if (b != cur) {
            atomicAdd(&g[cur * Hdim + f], s);
            s = 0.f;
            cur = b;
        }
        s += fmaxf(fmaf(h[(size_t)r * Hdim + f], sc, sh), 0.f);
    }
    atomicAdd(&g[cur * Hdim + f], s);
}

// ---------------- MLP head ----------------
__global__ void head_k(const float* __restrict__ g, const float* __restrict__ w1,
                       const float* __restrict__ b1, const float* __restrict__ w2,
                       const float* __restrict__ b2, float* __restrict__ out)
{
    __shared__ float gs[Hdim];
    __shared__ float zs[HD2];
    int b = blockIdx.x;
    int t = threadIdx.x;
    gs[t]       = g[b * Hdim + t];
    gs[t + 128] = g[b * Hdim + t + 128];
    __syncthreads();
    float acc = b1[t];
    for (int k = 0; k < Hdim; k++) acc = fmaf(gs[k], w1[k * HD2 + t], acc);
    zs[t] = fmaxf(acc, 0.f);
    __syncthreads();
    if (t < OUTdim) {
        float o = b2[t];
        for (int k = 0; k < HD2; k++) o = fmaf(zs[k], w2[k * OUTdim + t], o);
        out[b * OUTdim + t] = o;
    }
}

// ---------------- launch ----------------
extern "C" void kernel_launch(void* const* d_in, const int* in_sizes, int n_in,
                              void* d_out, int out_size)
{
    const float* x       = (const float*)d_in[0];
    const int*   ei      = (const int*)d_in[1];
    const int*   batch   = (const int*)d_in[2];
    const float* node_w  = (const float*)d_in[3];
    const float* node_b  = (const float*)d_in[4];
    const float* conv_w  = (const float*)d_in[5];
    const float* conv_b  = (const float*)d_in[6];
    const float* bn_g    = (const float*)d_in[7];
    const float* bn_b    = (const float*)d_in[8];
    const float* head_w1 = (const float*)d_in[9];
    const float* head_b1 = (const float*)d_in[10];
    const float* head_w2 = (const float*)d_in[11];
    const float* head_b2 = (const float*)d_in[12];
    float* out = (float*)d_out;

    int N = in_sizes[0] / INdim;
    int E = in_sizes[1] / 2;
    const int* rowi = ei;
    const int* coli = ei + E;

    float *bufA, *bufB, *dis, *scale, *shift, *pool;
    int *cnt, *rowptr, *cursor, *partial, *bsum;
    int2* csr;
    double* stats;
    cudaGetSymbolAddress((void**)&bufA, g_bufA);
    cudaGetSymbolAddress((void**)&bufB, g_bufB);
    cudaGetSymbolAddress((void**)&dis, g_dis);
    cudaGetSymbolAddress((void**)&cnt, g_cnt);
    cudaGetSymbolAddress((void**)&rowptr, g_rowptr);
    cudaGetSymbolAddress((void**)&cursor, g_cursor);
    cudaGetSymbolAddress((void**)&partial, g_partial);
    cudaGetSymbolAddress((void**)&bsum, g_bsum);
    cudaGetSymbolAddress((void**)&csr, g_csr);
    cudaGetSymbolAddress((void**)&stats, g_stats);
    cudaGetSymbolAddress((void**)&scale, g_scale);
    cudaGetSymbolAddress((void**)&shift, g_shift);
    cudaGetSymbolAddress((void**)&pool, g_pool);

    int nblk1 = (N + SCAN_B - 1) / SCAN_B;
    dim3 ggrid(2, (N + 127) / 128);

    // launches 1-4: zero, count, node gemm, conv gemm layer0 (#4 => profiled by ncu)
    zero_all_k<<<(N + 255) / 256, 256>>>(cnt, stats, pool, N);
    count_k<<<592, 256>>>(coli, cnt, E);
    gemm_k<<<ggrid, 256>>>(x, node_w, node_b, bufA, nullptr, nullptr, N, INdim);
    gemm_k<<<ggrid, 256>>>(bufA, conv_w, nullptr, bufB, nullptr, nullptr, N, Hdim);

    // CSR build
    scan1_k<<<nblk1, SCAN_B>>>(cnt, partial, bsum, N);
    scan2_k<<<1, SCAN_B>>>(bsum, nblk1);
    scan3_k<<<(N + 255) / 256, 256>>>(partial, bsum, cnt, rowptr, cursor, dis, N, E);
    fill_k<<<592, 256>>>(rowi, coli, dis, cursor, csr, E);

    int aggBlocks = 592;
    // layer 0 tail
    aggregate_k<<<aggBlocks, 256>>>(bufB, bufA, rowptr, csr, dis, conv_b, stats, N);
    bn_final_k<<<1, 256>>>(stats, bn_g, bn_b, scale, shift, N);

    // layers 1..2
    for (int l = 1; l < NLAY; l++) {
        gemm_k<<<ggrid, 256>>>(bufA, conv_w + (size_t)l * Hdim * Hdim, nullptr, bufB,
                               scale + (l - 1) * Hdim, shift + (l - 1) * Hdim, N, Hdim);
        aggregate_k<<<aggBlocks, 256>>>(bufB, bufA, rowptr, csr, dis,
                                        conv_b + l * Hdim, stats + l * 2 * Hdim, N);
        bn_final_k<<<1, 256>>>(stats + l * 2 * Hdim, bn_g + l * Hdim, bn_b + l * Hdim,
                               scale + l * Hdim, shift + l * Hdim, N);
    }

    // pool (applies layer-2 BN affine + relu) + head
    pool_k<<<(N + 255) / 256, 256>>>(bufA, batch, scale + 2 * Hdim, shift + 2 * Hdim,
                                     pool, N);
    head_k<<<NGRAPH, HD2>>>(pool, head_w1, head_b1, head_w2, head_b2, out);
}

// round 9
// speedup vs baseline: 1.6207x; 1.3148x over previous
#include <cuda_runtime.h>
#include <cuda_bf16.h>
#include <cstdint>
#include <math.h>

// ---------------- problem constants ----------------
constexpr int Hdim   = 256;
constexpr int INdim  = 64;
constexpr int HD2    = 128;
constexpr int OUTdim = 12;
constexpr int NLAY   = 3;
constexpr int NGRAPH = 64;
constexpr int NMAX   = 50000;
constexpr int EMAX   = 600000;
constexpr int SCAN_B = 512;
constexpr int MAXBLK1 = (NMAX + SCAN_B - 1) / SCAN_B;

// weight scratch: bf16 split + transposed [N][K]
constexpr int NODE_OFF = 0;                      // 256 x 64
constexpr int CONV_OFF = 256 * 64;               // 3 x (256 x 256)
constexpr int WTOT     = CONV_OFF + 3 * 256 * 256;

// ---------------- scratch (device globals, no allocation) ----------------
__device__ float  g_bufA[(size_t)NMAX * Hdim];
__device__ float  g_bufB[(size_t)NMAX * Hdim];
__device__ float  g_dis[NMAX];
__device__ int    g_cnt[NMAX];
__device__ int    g_rowptr[NMAX + 1];
__device__ int    g_cursor[NMAX];
__device__ int    g_partial[NMAX];
__device__ int    g_bsum[MAXBLK1 + 1];
__device__ int2   g_csr[EMAX];
__device__ double g_stats[NLAY * 2 * Hdim];
__device__ float  g_scale[NLAY * Hdim];
__device__ float  g_shift[NLAY * Hdim];
__device__ float  g_pool[NGRAPH * Hdim];
__device__ __nv_bfloat16 g_BtH[WTOT];
__device__ __nv_bfloat16 g_BtL[WTOT];

// ---------------- helpers ----------------
__device__ __forceinline__ uint32_t packbf2(float hi, float lo) {
    uint32_t d;
    asm("cvt.rn.bf16x2.f32 %0, %1, %2;" : "=r"(d) : "f"(hi), "f"(lo));
    return d;
}

// split pair (x0 = lower k, x1 = upper k) into hi/lo bf16x2 words
__device__ __forceinline__ void split2(float x0, float x1, uint32_t& h, uint32_t& l) {
    h = packbf2(x1, x0);
    float f0 = __uint_as_float(h << 16);
    float f1 = __uint_as_float(h & 0xFFFF0000u);
    l = packbf2(x1 - f1, x0 - f0);
}

#define MMA_BF16(d, a, b)                                                       \
    asm volatile("mma.sync.aligned.m16n8k16.row.col.f32.bf16.bf16.f32 "        \
                 "{%0,%1,%2,%3},{%4,%5,%6,%7},{%8,%9},{%0,%1,%2,%3};"          \
                 : "+f"(d[0]), "+f"(d[1]), "+f"(d[2]), "+f"(d[3])              \
                 : "r"(a[0]), "r"(a[1]), "r"(a[2]), "r"(a[3]),                 \
                   "r"(b[0]), "r"(b[1]))

// ---------------- weight pre-split+transpose (once per call) ----------------
__global__ void wsplit_k(const float* __restrict__ node_w,
                         const float* __restrict__ conv_w)
{
    int idx = blockIdx.x * blockDim.x + threadIdx.x;
    if (idx >= WTOT) return;
    float v;
    if (idx < CONV_OFF) {                 // node: Bt[n][k], k<64 ; src [k][n]
        int n = idx / INdim, k = idx % INdim;
        v = node_w[k * Hdim + n];
    } else {
        int rel = idx - CONV_OFF;
        int l = rel >> 16;
        int r2 = rel & 65535;
        int n = r2 >> 8, k = r2 & 255;
        v = conv_w[l * 65536 + k * Hdim + n];
    }
    __nv_bfloat16 h = __float2bfloat16(v);
    __nv_bfloat16 lo = __float2bfloat16(v - __bfloat162float(h));
    g_BtH[idx] = h;
    g_BtL[idx] = lo;
}

// ---------------- one-shot zeroing ----------------
__global__ void zero_all_k(int* cnt, double* stats, float* pool, int N) {
    int i = blockIdx.x * blockDim.x + threadIdx.x;
    if (i < N) cnt[i] = 0;
    if (i < NLAY * 2 * Hdim) stats[i] = 0.0;
    if (i < NGRAPH * Hdim) pool[i] = 0.0f;
}

// ---------------- CSR build ----------------
__global__ void count_k(const int* __restrict__ coli, int* __restrict__ cnt, int E) {
    int i = blockIdx.x * blockDim.x + threadIdx.x;
    int stride = gridDim.x * blockDim.x;
    for (int e = i; e < E; e += stride) atomicAdd(&cnt[coli[e]], 1);
}

__global__ void scan1_k(const int* __restrict__ cnt, int* __restrict__ partial,
                        int* __restrict__ bsum, int N)
{
    __shared__ int sh[SCAN_B];
    int t = threadIdx.x;
    int i = blockIdx.x * SCAN_B + t;
    int v = (i < N) ? cnt[i] : 0;
    sh[t] = v;
    __syncthreads();
#pragma unroll
    for (int off = 1; off < SCAN_B; off <<= 1) {
        int add = (t >= off) ? sh[t - off] : 0;
        __syncthreads();
        sh[t] += add;
        __syncthreads();
    }
    if (i < N) partial[i] = sh[t] - v;
    if (t == SCAN_B - 1) bsum[blockIdx.x] = sh[t];
}

__global__ void scan2_k(int* __restrict__ bsum, int nb) {
    __shared__ int sh[SCAN_B];
    int t = threadIdx.x;
    int v = (t < nb) ? bsum[t] : 0;
    sh[t] = v;
    __syncthreads();
#pragma unroll
    for (int off = 1; off < SCAN_B; off <<= 1) {
        int add = (t >= off) ? sh[t - off] : 0;
        __syncthreads();
        sh[t] += add;
        __syncthreads();
    }
    if (t < nb) bsum[t] = sh[t] - v;
}

__global__ void scan3_k(const int* __restrict__ partial, const int* __restrict__ bsum,
                        const int* __restrict__ cnt, int* __restrict__ rowptr,
                        int* __restrict__ cursor, float* __restrict__ dis, int N, int E)
{
    int i = blockIdx.x * blockDim.x + threadIdx.x;
    if (i < N) {
        int rp = partial[i] + bsum[i / SCAN_B];
        rowptr[i] = rp;
        cursor[i] = rp;
        dis[i] = rsqrtf((float)(cnt[i] + 1));
    }
    if (i == 0) rowptr[N] = E;
}

__global__ void fill_k(const int* __restrict__ rowi, const int* __restrict__ coli,
                       const float* __restrict__ dis, int* __restrict__ cursor,
                       int2* __restrict__ csr, int E)
{
    int i = blockIdx.x * blockDim.x + threadIdx.x;
    int stride = gridDim.x * blockDim.x;
    for (int e = i; e < E; e += stride) {
        int r = rowi[e], c = coli[e];
        int slot = atomicAdd(&cursor[c], 1);
        csr[slot] = make_int2(r, __float_as_int(dis[r] * dis[c]));
    }
}

// ---------------- tensor-core GEMM (bf16x3 split) -----------------------------
// C[M,256] = f(A)[M,K] @ W[K,256] (+bias), W pre-split+transposed as Bt[n][k].
// f(a) = relu(a*scale[k]+shift[k]) if scale != null.
// Block tile 128x64, 8 warps (4m x 2n), warp tile 32x32, BK=16.
constexpr int GBM = 128, GBN = 64, GBK = 16;
constexpr int PADW = 12;    // words per smem row (8 data + 4 pad, conflict-free)

__global__ __launch_bounds__(256, 2)
void gemm_tc_k(const float* __restrict__ A,
               const __nv_bfloat16* __restrict__ BtH,
               const __nv_bfloat16* __restrict__ BtL,
               const float* __restrict__ bias, float* __restrict__ C,
               const float* __restrict__ scale, const float* __restrict__ shift,
               int M, int K)
{
    __shared__ uint32_t AsH[2][GBM][PADW];
    __shared__ uint32_t AsL[2][GBM][PADW];
    __shared__ uint32_t BsH[2][GBN][PADW];
    __shared__ uint32_t BsL[2][GBN][PADW];

    int tid = threadIdx.x;
    int wid = tid >> 5, lane = tid & 31;
    int g = lane >> 2, t = lane & 3;
    int wm = wid & 3, wn = wid >> 2;

    int rowBase = blockIdx.y * GBM;
    int colBase = blockIdx.x * GBN;

    float acc[2][4][4];
#pragma unroll
    for (int m = 0; m < 2; m++)
#pragma unroll
        for (int na = 0; na < 4; na++)
#pragma unroll
            for (int c = 0; c < 4; c++) acc[m][na][c] = 0.0f;

    // A staging: thread -> row tid>>1, k-seg (tid&1)*8 (8 elems = 2 float4)
    int aRow = tid >> 1;
    int aSeg = (tid & 1) * 8;
    bool aValid = (rowBase + aRow) < M;
    const float* Aptr = A + (size_t)(rowBase + aRow) * K + aSeg;

    // B staging: thread -> n tid>>2, k-seg (tid&3)*4 (4 bf16 = uint2)
    int bN = tid >> 2;
    int bSeg = (tid & 3) * 4;
    const __nv_bfloat16* BHp = BtH + (size_t)(colBase + bN) * K + bSeg;
    const __nv_bfloat16* BLp = BtL + (size_t)(colBase + bN) * K + bSeg;

    auto loadA = [&](int k0, float4& v0, float4& v1) {
        if (aValid) {
            v0 = *(const float4*)(Aptr + k0);
            v1 = *(const float4*)(Aptr + k0 + 4);
        } else {
            v0 = make_float4(0.f, 0.f, 0.f, 0.f);
            v1 = v0;
        }
        if (scale) {
            float4 sc0 = *(const float4*)(scale + k0 + aSeg);
            float4 sc1 = *(const float4*)(scale + k0 + aSeg + 4);
            float4 sh0 = *(const float4*)(shift + k0 + aSeg);
            float4 sh1 = *(const float4*)(shift + k0 + aSeg + 4);
            v0.x = fmaxf(fmaf(v0.x, sc0.x, sh0.x), 0.f);
            v0.y = fmaxf(fmaf(v0.y, sc0.y, sh0.y), 0.f);
            v0.z = fmaxf(fmaf(v0.z, sc0.z, sh0.z), 0.f);
            v0.w = fmaxf(fmaf(v0.w, sc0.w, sh0.w), 0.f);
            v1.x = fmaxf(fmaf(v1.x, sc1.x, sh1.x), 0.f);
            v1.y = fmaxf(fmaf(v1.y, sc1.y, sh1.y), 0.f);
            v1.z = fmaxf(fmaf(v1.z, sc1.z, sh1.z), 0.f);
            v1.w = fmaxf(fmaf(v1.w, sc1.w, sh1.w), 0.f);
        }
    };

    auto storeA = [&](int buf, const float4& v0, const float4& v1) {
        int w0 = (tid & 1) * 4;
        uint32_t h, l;
        split2(v0.x, v0.y, h, l); AsH[buf][aRow][w0 + 0] = h; AsL[buf][aRow][w0 + 0] = l;
        split2(v0.z, v0.w, h, l); AsH[buf][aRow][w0 + 1] = h; AsL[buf][aRow][w0 + 1] = l;
        split2(v1.x, v1.y, h, l); AsH[buf][aRow][w0 + 2] = h; AsL[buf][aRow][w0 + 2] = l;
        split2(v1.z, v1.w, h, l); AsH[buf][aRow][w0 + 3] = h; AsL[buf][aRow][w0 + 3] = l;
    };

    auto storeB = [&](int buf, uint2 uh, uint2 ul) {
        int w0 = (tid & 3) * 2;
        BsH[buf][bN][w0]     = uh.x;
        BsH[buf][bN][w0 + 1] = uh.y;
        BsL[buf][bN][w0]     = ul.x;
        BsL[buf][bN][w0 + 1] = ul.y;
    };

    // prologue: tile 0
    {
        float4 v0, v1;
        loadA(0, v0, v1);
        uint2 uh = *(const uint2*)BHp;
        uint2 ul = *(const uint2*)BLp;
        storeA(0, v0, v1);
        storeB(0, uh, ul);
    }
    __syncthreads();

    int nT = K / GBK;
    for (int tt = 0; tt < nT; tt++) {
        int buf = tt & 1;
        float4 v0, v1;
        uint2 uh, ul;
        bool more = (tt + 1) < nT;
        if (more) {
            int k0 = (tt + 1) * GBK;
            loadA(k0, v0, v1);
            uh = *(const uint2*)(BHp + k0);
            ul = *(const uint2*)(BLp + k0);
        }

        // fragments
        uint32_t aH[2][4], aL[2][4], bHf[4][2], bLf[4][2];
#pragma unroll
        for (int m = 0; m < 2; m++) {
            int r = wm * 32 + m * 16 + g;
            aH[m][0] = AsH[buf][r][t];
            aH[m][1] = AsH[buf][r + 8][t];
            aH[m][2] = AsH[buf][r][t + 4];
            aH[m][3] = AsH[buf][r + 8][t + 4];
            aL[m][0] = AsL[buf][r][t];
            aL[m][1] = AsL[buf][r + 8][t];
            aL[m][2] = AsL[buf][r][t + 4];
            aL[m][3] = AsL[buf][r + 8][t + 4];
        }
#pragma unroll
        for (int na = 0; na < 4; na++) {
            int n0 = wn * 32 + na * 8 + g;
            bHf[na][0] = BsH[buf][n0][t];
            bHf[na][1] = BsH[buf][n0][t + 4];
            bLf[na][0] = BsL[buf][n0][t];
            bLf[na][1] = BsL[buf][n0][t + 4];
        }
#pragma unroll
        for (int m = 0; m < 2; m++)
#pragma unroll
            for (int na = 0; na < 4; na++) {
                MMA_BF16(acc[m][na], aH[m], bHf[na]);
                MMA_BF16(acc[m][na], aH[m], bLf[na]);
                MMA_BF16(acc[m][na], aL[m], bHf[na]);
            }

        if (more) {
            storeA(buf ^ 1, v0, v1);
            storeB(buf ^ 1, uh, ul);
        }
        __syncthreads();
    }

    // epilogue
#pragma unroll
    for (int m = 0; m < 2; m++) {
        int r0 = rowBase + wm * 32 + m * 16 + g;
#pragma unroll
        for (int na = 0; na < 4; na++) {
            int col = colBase + wn * 32 + na * 8 + 2 * t;
            float b0 = 0.f, b1 = 0.f;
            if (bias) { b0 = bias[col]; b1 = bias[col + 1]; }
            if (r0 < M) {
                float2 v = make_float2(acc[m][na][0] + b0, acc[m][na][1] + b1);
                *(float2*)&C[(size_t)r0 * Hdim + col] = v;
            }
            if (r0 + 8 < M) {
                float2 v = make_float2(acc[m][na][2] + b0, acc[m][na][3] + b1);
                *(float2*)&C[(size_t)(r0 + 8) * Hdim + col] = v;
            }
        }
    }
}

// ---------------- aggregate v2: 2 warps/node, packed csr, fused BN stats -------
__device__ __forceinline__ void fma4(float4& a, const float4& v, float s) {
    a.x = fmaf(v.x, s, a.x); a.y = fmaf(v.y, s, a.y);
    a.z = fmaf(v.z, s, a.z); a.w = fmaf(v.w, s, a.w);
}

__global__ __launch_bounds__(256)
void aggregate_k(const float* __restrict__ hw, float* __restrict__ agg,
                 const int* __restrict__ rowptr, const int2* __restrict__ csr,
                 const float* __restrict__ dis,
                 const float* __restrict__ convb, double* __restrict__ stats, int N)
{
    __shared__ float4 sh_s[8][32];
    __shared__ float4 sh_q[8][32];

    int tid = threadIdx.x;
    int wid = tid >> 5;
    int lane = tid & 31;

    int gw = blockIdx.x * 8 + wid;
    int half = gw & 1;
    int rowOff = half * 32 + lane;

    float4 bseg = ((const float4*)convb)[rowOff];
    float4 tsum = make_float4(0, 0, 0, 0);
    float4 tsq  = make_float4(0, 0, 0, 0);

    int nodeStride = gridDim.x * 4;

    for (int n = gw >> 1; n < N; n += nodeStride) {
        float dn = __ldg(dis + n);
        float sn = dn * dn;
        float4 acc = bseg;
        fma4(acc, ((const float4*)(hw + (size_t)n * Hdim))[rowOff], sn);

        int j  = __ldg(rowptr + n);
        int e1 = __ldg(rowptr + n + 1);

        for (; j + 3 < e1; j += 4) {
            int2 p0 = __ldg(csr + j);
            int2 p1 = __ldg(csr + j + 1);
            int2 p2 = __ldg(csr + j + 2);
            int2 p3 = __ldg(csr + j + 3);
            float4 v0 = ((const float4*)(hw + (size_t)p0.x * Hdim))[rowOff];
            float4 v1 = ((const float4*)(hw + (size_t)p1.x * Hdim))[rowOff];
            float4 v2 = ((const float4*)(hw + (size_t)p2.x * Hdim))[rowOff];
            float4 v3 = ((const float4*)(hw + (size_t)p3.x * Hdim))[rowOff];
            fma4(acc, v0, __int_as_float(p0.y));
            fma4(acc, v1, __int_as_float(p1.y));
            fma4(acc, v2, __int_as_float(p2.y));
            fma4(acc, v3, __int_as_float(p3.y));
        }
        for (; j < e1; j++) {
            int2 p = __ldg(csr + j);
            float4 v = ((const float4*)(hw + (size_t)p.x * Hdim))[rowOff];
            fma4(acc, v, __int_as_float(p.y));
        }

        ((float4*)(agg + (size_t)n * Hdim))[rowOff] = acc;

        tsum.x += acc.x; tsum.y += acc.y; tsum.z += acc.z; tsum.w += acc.w;
        tsq.x = fmaf(acc.x, acc.x, tsq.x); tsq.y = fmaf(acc.y, acc.y, tsq.y);
        tsq.z = fmaf(acc.z, acc.z, tsq.z); tsq.w = fmaf(acc.w, acc.w, tsq.w);
    }

    sh_s[wid][lane] = tsum;
    sh_q[wid][lane] = tsq;
    __syncthreads();

    int f = tid;
    int f4 = f >> 2, comp = f & 3;
    int hf = f4 >> 5, l = f4 & 31;
    float s = 0.f, q = 0.f;
#pragma unroll
    for (int k = 0; k < 4; k++) {
        int w = hf + 2 * k;
        s += ((const float*)&sh_s[w][l])[comp];
        q += ((const float*)&sh_q[w][l])[comp];
    }
    atomicAdd(&stats[f], (double)s);
    atomicAdd(&stats[Hdim + f], (double)q);
}

// ---------------- bn scale/shift ----------------
__global__ void bn_final_k(const double* __restrict__ stats,
                           const float* __restrict__ gamma, const float* __restrict__ beta,
                           float* __restrict__ scale, float* __restrict__ shift, int N)
{
    int f = threadIdx.x;
    double mean = stats[f] / N;
    double var = stats[Hdim + f] / N - mean * mean;
    float sc = gamma[f] * rsqrtf((float)var + 1e-5f);
    scale[f] = sc;
    shift[f] = beta[f] - (float)mean * sc;
}

// ---------------- global add pool with fused BN affine + ReLU ----------------
__global__ void pool_k(const float* __restrict__ h, const int* __restrict__ batch,
                       const float* __restrict__ scale, const float* __restrict__ shift,
                       float* __restrict__ g, int N)
{
    constexpr int CH = 256;
    int f = threadIdx.x;
    int r0 = blockIdx.x * CH;
    int r1 = min(N, r0 + CH);
    if (r0 >= N) return;
    float sc = scale[f], sh = shift[f];
    int cur = batch[r0];
    float s = 0.f;
    for (int r = r0; r < r1; r++) {
        int b = batch[r];
        if (b != cur) {
            atomicAdd(&g[cur * Hdim + f], s);
            s = 0.f;
            cur = b;
        }
        s += fmaxf(fmaf(h[(size_t)r * Hdim + f], sc, sh), 0.f);
    }
    atomicAdd(&g[cur * Hdim + f], s);
}

// ---------------- MLP head ----------------
__global__ void head_k(const float* __restrict__ g, const float* __restrict__ w1,
                       const float* __restrict__ b1, const float* __restrict__ w2,
                       const float* __restrict__ b2, float* __restrict__ out)
{
    __shared__ float gs[Hdim];
    __shared__ float zs[HD2];
    int b = blockIdx.x;
    int t = threadIdx.x;
    gs[t]       = g[b * Hdim + t];
    gs[t + 128] = g[b * Hdim + t + 128];
    __syncthreads();
    float acc = b1[t];
    for (int k = 0; k < Hdim; k++) acc = fmaf(gs[k], w1[k * HD2 + t], acc);
    zs[t] = fmaxf(acc, 0.f);
    __syncthreads();
    if (t < OUTdim) {
        float o = b2[t];
        for (int k = 0; k < HD2; k++) o = fmaf(zs[k], w2[k * OUTdim + t], o);
        out[b * OUTdim + t] = o;
    }
}

// ---------------- launch ----------------
extern "C" void kernel_launch(void* const* d_in, const int* in_sizes, int n_in,
                              void* d_out, int out_size)
{
    const float* x       = (const float*)d_in[0];
    const int*   ei      = (const int*)d_in[1];
    const int*   batch   = (const int*)d_in[2];
    const float* node_w  = (const float*)d_in[3];
    const float* node_b  = (const float*)d_in[4];
    const float* conv_w  = (const float*)d_in[5];
    const float* conv_b  = (const float*)d_in[6];
    const float* bn_g    = (const float*)d_in[7];
    const float* bn_b    = (const float*)d_in[8];
    const float* head_w1 = (const float*)d_in[9];
    const float* head_b1 = (const float*)d_in[10];
    const float* head_w2 = (const float*)d_in[11];
    const float* head_b2 = (const float*)d_in[12];
    float* out = (float*)d_out;

    int N = in_sizes[0] / INdim;
    int E = in_sizes[1] / 2;
    const int* rowi = ei;
    const int* coli = ei + E;

    float *bufA, *bufB, *dis, *scale, *shift, *pool;
    int *cnt, *rowptr, *cursor, *partial, *bsum;
    int2* csr;
    double* stats;
    __nv_bfloat16 *BtH, *BtL;
    cudaGetSymbolAddress((void**)&bufA, g_bufA);
    cudaGetSymbolAddress((void**)&bufB, g_bufB);
    cudaGetSymbolAddress((void**)&dis, g_dis);
    cudaGetSymbolAddress((void**)&cnt, g_cnt);
    cudaGetSymbolAddress((void**)&rowptr, g_rowptr);
    cudaGetSymbolAddress((void**)&cursor, g_cursor);
    cudaGetSymbolAddress((void**)&partial, g_partial);
    cudaGetSymbolAddress((void**)&bsum, g_bsum);
    cudaGetSymbolAddress((void**)&csr, g_csr);
    cudaGetSymbolAddress((void**)&stats, g_stats);
    cudaGetSymbolAddress((void**)&scale, g_scale);
    cudaGetSymbolAddress((void**)&shift, g_shift);
    cudaGetSymbolAddress((void**)&pool, g_pool);
    cudaGetSymbolAddress((void**)&BtH, g_BtH);
    cudaGetSymbolAddress((void**)&BtL, g_BtL);

    int nblk1 = (N + SCAN_B - 1) / SCAN_B;
    dim3 ggrid(Hdim / GBN, (N + GBM - 1) / GBM);   // (4, 391)

    // 1: zero, 2: weight split, 3: node gemm, 4: conv gemm l0 (profiled slot)
    zero_all_k<<<(N + 255) / 256, 256>>>(cnt, stats, pool, N);
    wsplit_k<<<(WTOT + 255) / 256, 256>>>(node_w, conv_w);
    gemm_tc_k<<<ggrid, 256>>>(x, BtH + NODE_OFF, BtL + NODE_OFF, node_b, bufA,
                              nullptr, nullptr, N, INdim);
    gemm_tc_k<<<ggrid, 256>>>(bufA, BtH + CONV_OFF, BtL + CONV_OFF, nullptr, bufB,
                              nullptr, nullptr, N, Hdim);

    // CSR build
    count_k<<<592, 256>>>(coli, cnt, E);
    scan1_k<<<nblk1, SCAN_B>>>(cnt, partial, bsum, N);
    scan2_k<<<1, SCAN_B>>>(bsum, nblk1);
    scan3_k<<<(N + 255) / 256, 256>>>(partial, bsum, cnt, rowptr, cursor, dis, N, E);
    fill_k<<<592, 256>>>(rowi, coli, dis, cursor, csr, E);

    int aggBlocks = 592;
    // layer 0 tail
    aggregate_k<<<aggBlocks, 256>>>(bufB, bufA, rowptr, csr, dis, conv_b, stats, N);
    bn_final_k<<<1, 256>>>(stats, bn_g, bn_b, scale, shift, N);

    // layers 1..2
    for (int l = 1; l < NLAY; l++) {
        gemm_tc_k<<<ggrid, 256>>>(bufA, BtH + CONV_OFF + l * 65536,
                                  BtL + CONV_OFF + l * 65536, nullptr, bufB,
                                  scale + (l - 1) * Hdim, shift + (l - 1) * Hdim,
                                  N, Hdim);
        aggregate_k<<<aggBlocks, 256>>>(bufB, bufA, rowptr, csr, dis,
                                        conv_b + l * Hdim, stats + l * 2 * Hdim, N);
        bn_final_k<<<1, 256>>>(stats + l * 2 * Hdim, bn_g + l * Hdim, bn_b + l * Hdim,
                               scale + l * Hdim, shift + l * Hdim, N);
    }

    // pool (applies layer-2 BN affine + relu) + head
    pool_k<<<(N + 255) / 256, 256>>>(bufA, batch, scale + 2 * Hdim, shift + 2 * Hdim,
                                     pool, N);
    head_k<<<NGRAPH, HD2>>>(pool, head_w1, head_b1, head_w2, head_b2, out);
}

// round 10
// speedup vs baseline: 1.6625x; 1.0258x over previous
#include <cuda_runtime.h>
#include <cuda_bf16.h>
#include <cstdint>
#include <math.h>

// ---------------- problem constants ----------------
constexpr int Hdim   = 256;
constexpr int INdim  = 64;
constexpr int HD2    = 128;
constexpr int OUTdim = 12;
constexpr int NLAY   = 3;
constexpr int NGRAPH = 64;
constexpr int NMAX   = 50000;
constexpr int EMAX   = 600000;
constexpr int SCAN_B = 512;
constexpr int MAXBLK1 = (NMAX + SCAN_B - 1) / SCAN_B;

// weight scratch: bf16 split + transposed [N][K]
constexpr int NODE_OFF = 0;                      // 256 x 64
constexpr int CONV_OFF = 256 * 64;               // 3 x (256 x 256)
constexpr int WTOT     = CONV_OFF + 3 * 256 * 256;

// ---------------- scratch (device globals, no allocation) ----------------
__device__ float  g_bufA[(size_t)NMAX * Hdim];
__device__ float  g_bufB[(size_t)NMAX * Hdim];
__device__ float  g_dis[NMAX];
__device__ int    g_cnt[NMAX];
__device__ int    g_rowptr[NMAX + 1];
__device__ int    g_cursor[NMAX];
__device__ int    g_partial[NMAX];
__device__ int    g_bsum[MAXBLK1 + 1];
__device__ int2   g_csr[EMAX];
__device__ double g_stats[NLAY * 2 * Hdim];
__device__ float  g_scale[NLAY * Hdim];
__device__ float  g_shift[NLAY * Hdim];
__device__ float  g_pool[NGRAPH * Hdim];
__device__ __nv_bfloat16 g_BtH[WTOT];
__device__ __nv_bfloat16 g_BtL[WTOT];

// ---------------- helpers ----------------
__device__ __forceinline__ uint32_t packbf2(float hi, float lo) {
    uint32_t d;
    asm("cvt.rn.bf16x2.f32 %0, %1, %2;" : "=r"(d) : "f"(hi), "f"(lo));
    return d;
}

// split pair (x0 = lower k, x1 = upper k) into hi/lo bf16x2 words
__device__ __forceinline__ void split2(float x0, float x1, uint32_t& h, uint32_t& l) {
    h = packbf2(x1, x0);
    float f0 = __uint_as_float(h << 16);
    float f1 = __uint_as_float(h & 0xFFFF0000u);
    l = packbf2(x1 - f1, x0 - f0);
}

#define MMA_BF16(d, a, b)                                                       \
    asm volatile("mma.sync.aligned.m16n8k16.row.col.f32.bf16.bf16.f32 "        \
                 "{%0,%1,%2,%3},{%4,%5,%6,%7},{%8,%9},{%0,%1,%2,%3};"          \
                 : "+f"(d[0]), "+f"(d[1]), "+f"(d[2]), "+f"(d[3])              \
                 : "r"(a[0]), "r"(a[1]), "r"(a[2]), "r"(a[3]),                 \
                   "r"(b[0]), "r"(b[1]))

__device__ __forceinline__ void ldsm_x4(uint32_t& r0, uint32_t& r1,
                                        uint32_t& r2, uint32_t& r3, uint32_t addr) {
    asm volatile("ldmatrix.sync.aligned.m8n8.x4.shared.b16 {%0,%1,%2,%3}, [%4];"
                 : "=r"(r0), "=r"(r1), "=r"(r2), "=r"(r3) : "r"(addr));
}

// ---------------- weight pre-split+transpose (once per call) ----------------
__global__ void wsplit_k(const float* __restrict__ node_w,
                         const float* __restrict__ conv_w)
{
    int idx = blockIdx.x * blockDim.x + threadIdx.x;
    if (idx >= WTOT) return;
    float v;
    if (idx < CONV_OFF) {                 // node: Bt[n][k], k<64 ; src [k][n]
        int n = idx / INdim, k = idx % INdim;
        v = node_w[k * Hdim + n];
    } else {
        int rel = idx - CONV_OFF;
        int l = rel >> 16;
        int r2 = rel & 65535;
        int n = r2 >> 8, k = r2 & 255;
        v = conv_w[l * 65536 + k * Hdim + n];
    }
    __nv_bfloat16 h = __float2bfloat16(v);
    __nv_bfloat16 lo = __float2bfloat16(v - __bfloat162float(h));
    g_BtH[idx] = h;
    g_BtL[idx] = lo;
}

// ---------------- one-shot zeroing ----------------
__global__ void zero_all_k(int* cnt, double* stats, float* pool, int N) {
    int i = blockIdx.x * blockDim.x + threadIdx.x;
    if (i < N) cnt[i] = 0;
    if (i < NLAY * 2 * Hdim) stats[i] = 0.0;
    if (i < NGRAPH * Hdim) pool[i] = 0.0f;
}

// ---------------- CSR build ----------------
__global__ void count_k(const int* __restrict__ coli, int* __restrict__ cnt, int E) {
    int i = blockIdx.x * blockDim.x + threadIdx.x;
    int stride = gridDim.x * blockDim.x;
    for (int e = i; e < E; e += stride) atomicAdd(&cnt[coli[e]], 1);
}

__global__ void scan1_k(const int* __restrict__ cnt, int* __restrict__ partial,
                        int* __restrict__ bsum, int N)
{
    __shared__ int sh[SCAN_B];
    int t = threadIdx.x;
    int i = blockIdx.x * SCAN_B + t;
    int v = (i < N) ? cnt[i] : 0;
    sh[t] = v;
    __syncthreads();
#pragma unroll
    for (int off = 1; off < SCAN_B; off <<= 1) {
        int add = (t >= off) ? sh[t - off] : 0;
        __syncthreads();
        sh[t] += add;
        __syncthreads();
    }
    if (i < N) partial[i] = sh[t] - v;
    if (t == SCAN_B - 1) bsum[blockIdx.x] = sh[t];
}

__global__ void scan2_k(int* __restrict__ bsum, int nb) {
    __shared__ int sh[SCAN_B];
    int t = threadIdx.x;
    int v = (t < nb) ? bsum[t] : 0;
    sh[t] = v;
    __syncthreads();
#pragma unroll
    for (int off = 1; off < SCAN_B; off <<= 1) {
        int add = (t >= off) ? sh[t - off] : 0;
        __syncthreads();
        sh[t] += add;
        __syncthreads();
    }
    if (t < nb) bsum[t] = sh[t] - v;
}

__global__ void scan3_k(const int* __restrict__ partial, const int* __restrict__ bsum,
                        const int* __restrict__ cnt, int* __restrict__ rowptr,
                        int* __restrict__ cursor, float* __restrict__ dis, int N, int E)
{
    int i = blockIdx.x * blockDim.x + threadIdx.x;
    if (i < N) {
        int rp = partial[i] + bsum[i / SCAN_B];
        rowptr[i] = rp;
        cursor[i] = rp;
        dis[i] = rsqrtf((float)(cnt[i] + 1));
    }
    if (i == 0) rowptr[N] = E;
}

__global__ void fill_k(const int* __restrict__ rowi, const int* __restrict__ coli,
                       const float* __restrict__ dis, int* __restrict__ cursor,
                       int2* __restrict__ csr, int E)
{
    int i = blockIdx.x * blockDim.x + threadIdx.x;
    int stride = gridDim.x * blockDim.x;
    for (int e = i; e < E; e += stride) {
        int r = rowi[e], c = coli[e];
        int slot = atomicAdd(&cursor[c], 1);
        csr[slot] = make_int2(r, __float_as_int(dis[r] * dis[c]));
    }
}

// ---------------- tensor-core GEMM (bf16x3 split, ldmatrix) -------------------
// C[M,256] = f(A)[M,K] @ W[K,256] (+bias), W pre-split+transposed as Bt[n][k].
// f(a) = relu(a*scale[k]+shift[k]) if scale != null.
// Block tile 128x64, 8 warps (4m x 2n), warp tile 32x32, BK=16.
constexpr int GBM = 128, GBN = 64, GBK = 16;
constexpr int PADW = 12;    // words per smem row (8 data + 4 pad, conflict-free)

__global__ __launch_bounds__(256, 2)
void gemm_tc_k(const float* __restrict__ A,
               const __nv_bfloat16* __restrict__ BtH,
               const __nv_bfloat16* __restrict__ BtL,
               const float* __restrict__ bias, float* __restrict__ C,
               const float* __restrict__ scale, const float* __restrict__ shift,
               int M, int K)
{
    __shared__ uint32_t AsH[2][GBM][PADW];
    __shared__ uint32_t AsL[2][GBM][PADW];
    __shared__ uint32_t BsH[2][GBN][PADW];
    __shared__ uint32_t BsL[2][GBN][PADW];

    int tid = threadIdx.x;
    int wid = tid >> 5, lane = tid & 31;
    int g = lane >> 2, t = lane & 3;
    int wm = wid & 3, wn = wid >> 2;

    int rowBase = blockIdx.y * GBM;
    int colBase = blockIdx.x * GBN;

    float acc[2][4][4];
#pragma unroll
    for (int m = 0; m < 2; m++)
#pragma unroll
        for (int na = 0; na < 4; na++)
#pragma unroll
            for (int c = 0; c < 4; c++) acc[m][na][c] = 0.0f;

    // ---- ldmatrix lane addressing (constant across k-loop) ----
    int lr = lane & 7;
    int sel = lane >> 3;                       // matrix index 0..3
    // A x4: m0=rows+0..7/k0, m1=rows+8..15/k0, m2=rows/k8, m3=rows+8/k8
    int aRowF  = wm * 32 + (sel & 1) * 8 + lr;
    int aWordF = (sel >> 1) * 4;
    // B x4: m0=n+0..7/k0, m1=n/k8, m2=n+8/k0, m3=n+8/k8  (per 16-n pair)
    int bRowF  = wn * 32 + (sel >> 1) * 8 + lr;
    int bWordF = (sel & 1) * 4;

    constexpr uint32_t A_BUF = GBM * PADW * 4;   // 6144 B
    constexpr uint32_t B_BUF = GBN * PADW * 4;   // 3072 B
    constexpr uint32_t A_MSTEP = 16 * PADW * 4;  // 768 B per m-tile
    constexpr uint32_t B_PSTEP = 16 * PADW * 4;  // 768 B per 16-n pair

    uint32_t aAddrH = (uint32_t)__cvta_generic_to_shared(AsH) + (aRowF * PADW + aWordF) * 4;
    uint32_t aAddrL = (uint32_t)__cvta_generic_to_shared(AsL) + (aRowF * PADW + aWordF) * 4;
    uint32_t bAddrH = (uint32_t)__cvta_generic_to_shared(BsH) + (bRowF * PADW + bWordF) * 4;
    uint32_t bAddrL = (uint32_t)__cvta_generic_to_shared(BsL) + (bRowF * PADW + bWordF) * 4;

    // A staging: thread -> row tid>>1, k-seg (tid&1)*8 (8 elems = 2 float4)
    int aRow = tid >> 1;
    int aSeg = (tid & 1) * 8;
    bool aValid = (rowBase + aRow) < M;
    const float* Aptr = A + (size_t)(rowBase + aRow) * K + aSeg;

    // B staging: thread -> n tid>>2, k-seg (tid&3)*4 (4 bf16 = uint2)
    int bN = tid >> 2;
    const __nv_bfloat16* BHp = BtH + (size_t)(colBase + bN) * K + (tid & 3) * 4;
    const __nv_bfloat16* BLp = BtL + (size_t)(colBase + bN) * K + (tid & 3) * 4;

    auto loadA = [&](int k0, float4& v0, float4& v1) {
        if (aValid) {
            v0 = *(const float4*)(Aptr + k0);
            v1 = *(const float4*)(Aptr + k0 + 4);
        } else {
            v0 = make_float4(0.f, 0.f, 0.f, 0.f);
            v1 = v0;
        }
        if (scale) {
            float4 sc0 = *(const float4*)(scale + k0 + aSeg);
            float4 sc1 = *(const float4*)(scale + k0 + aSeg + 4);
            float4 sh0 = *(const float4*)(shift + k0 + aSeg);
            float4 sh1 = *(const float4*)(shift + k0 + aSeg + 4);
            v0.x = fmaxf(fmaf(v0.x, sc0.x, sh0.x), 0.f);
            v0.y = fmaxf(fmaf(v0.y, sc0.y, sh0.y), 0.f);
            v0.z = fmaxf(fmaf(v0.z, sc0.z, sh0.z), 0.f);
            v0.w = fmaxf(fmaf(v0.w, sc0.w, sh0.w), 0.f);
            v1.x = fmaxf(fmaf(v1.x, sc1.x, sh1.x), 0.f);
            v1.y = fmaxf(fmaf(v1.y, sc1.y, sh1.y), 0.f);
            v1.z = fmaxf(fmaf(v1.z, sc1.z, sh1.z), 0.f);
            v1.w = fmaxf(fmaf(v1.w, sc1.w, sh1.w), 0.f);
        }
    };

    auto storeA = [&](int buf, const float4& v0, const float4& v1) {
        int w0 = (tid & 1) * 4;
        uint32_t h, l;
        split2(v0.x, v0.y, h, l); AsH[buf][aRow][w0 + 0] = h; AsL[buf][aRow][w0 + 0] = l;
        split2(v0.z, v0.w, h, l); AsH[buf][aRow][w0 + 1] = h; AsL[buf][aRow][w0 + 1] = l;
        split2(v1.x, v1.y, h, l); AsH[buf][aRow][w0 + 2] = h; AsL[buf][aRow][w0 + 2] = l;
        split2(v1.z, v1.w, h, l); AsH[buf][aRow][w0 + 3] = h; AsL[buf][aRow][w0 + 3] = l;
    };

    auto storeB = [&](int buf, uint2 uh, uint2 ul) {
        int w0 = (tid & 3) * 2;
        BsH[buf][bN][w0]     = uh.x;
        BsH[buf][bN][w0 + 1] = uh.y;
        BsL[buf][bN][w0]     = ul.x;
        BsL[buf][bN][w0 + 1] = ul.y;
    };

    // prologue: tile 0
    {
        float4 v0, v1;
        loadA(0, v0, v1);
        uint2 uh = *(const uint2*)BHp;
        uint2 ul = *(const uint2*)BLp;
        storeA(0, v0, v1);
        storeB(0, uh, ul);
    }
    __syncthreads();

    int nT = K / GBK;
    for (int tt = 0; tt < nT; tt++) {
        int buf = tt & 1;
        float4 v0, v1;
        uint2 uh, ul;
        bool more = (tt + 1) < nT;
        if (more) {
            int k0 = (tt + 1) * GBK;
            loadA(k0, v0, v1);
            uh = *(const uint2*)(BHp + k0);
            ul = *(const uint2*)(BLp + k0);
        }

        // fragments via ldmatrix (8 x LDSM.x4 per warp)
        uint32_t aH[2][4], aL[2][4], bHf[4][2], bLf[4][2];
        uint32_t aOff = buf * A_BUF, bOff = buf * B_BUF;
#pragma unroll
        for (int m = 0; m < 2; m++) {
            ldsm_x4(aH[m][0], aH[m][1], aH[m][2], aH[m][3], aAddrH + aOff + m * A_MSTEP);
            ldsm_x4(aL[m][0], aL[m][1], aL[m][2], aL[m][3], aAddrL + aOff + m * A_MSTEP);
        }
#pragma unroll
        for (int p = 0; p < 2; p++) {
            ldsm_x4(bHf[2 * p][0], bHf[2 * p][1], bHf[2 * p + 1][0], bHf[2 * p + 1][1],
                    bAddrH + bOff + p * B_PSTEP);
            ldsm_x4(bLf[2 * p][0], bLf[2 * p][1], bLf[2 * p + 1][0], bLf[2 * p + 1][1],
                    bAddrL + bOff + p * B_PSTEP);
        }

        // pass-major: 8 independent MMAs between reuses of each accumulator
#pragma unroll
        for (int m = 0; m < 2; m++)
#pragma unroll
            for (int na = 0; na < 4; na++) MMA_BF16(acc[m][na], aH[m], bHf[na]);
#pragma unroll
        for (int m = 0; m < 2; m++)
#pragma unroll
            for (int na = 0; na < 4; na++) MMA_BF16(acc[m][na], aH[m], bLf[na]);
#pragma unroll
        for (int m = 0; m < 2; m++)
#pragma unroll
            for (int na = 0; na < 4; na++) MMA_BF16(acc[m][na], aL[m], bHf[na]);

        if (more) {
            storeA(buf ^ 1, v0, v1);
            storeB(buf ^ 1, uh, ul);
        }
        __syncthreads();
    }

    // epilogue
#pragma unroll
    for (int m = 0; m < 2; m++) {
        int r0 = rowBase + wm * 32 + m * 16 + g;
#pragma unroll
        for (int na = 0; na < 4; na++) {
            int col = colBase + wn * 32 + na * 8 + 2 * t;
            float b0 = 0.f, b1 = 0.f;
            if (bias) { b0 = bias[col]; b1 = bias[col + 1]; }
            if (r0 < M) {
                float2 v = make_float2(acc[m][na][0] + b0, acc[m][na][1] + b1);
                *(float2*)&C[(size_t)r0 * Hdim + col] = v;
            }
            if (r0 + 8 < M) {
                float2 v = make_float2(acc[m][na][2] + b0, acc[m][na][3] + b1);
                *(float2*)&C[(size_t)(r0 + 8) * Hdim + col] = v;
            }
        }
    }
}

// ---------------- aggregate v2: 2 warps/node, packed csr, fused BN stats -------
__device__ __forceinline__ void fma4(float4& a, const float4& v, float s) {
    a.x = fmaf(v.x, s, a.x); a.y = fmaf(v.y, s, a.y);
    a.z = fmaf(v.z, s, a.z); a.w = fmaf(v.w, s, a.w);
}

__global__ __launch_bounds__(256)
void aggregate_k(const float* __restrict__ hw, float* __restrict__ agg,
                 const int* __restrict__ rowptr, const int2* __restrict__ csr,
                 const float* __restrict__ dis,
                 const float* __restrict__ convb, double* __restrict__ stats, int N)
{
    __shared__ float4 sh_s[8][32];
    __shared__ float4 sh_q[8][32];

    int tid = threadIdx.x;
    int wid = tid >> 5;
    int lane = tid & 31;

    int gw = blockIdx.x * 8 + wid;
    int half = gw & 1;
    int rowOff = half * 32 + lane;

    float4 bseg = ((const float4*)convb)[rowOff];
    float4 tsum = make_float4(0, 0, 0, 0);
    float4 tsq  = make_float4(0, 0, 0, 0);

    int nodeStride = gridDim.x * 4;

    for (int n = gw >> 1; n < N; n += nodeStride) {
        float dn = __ldg(dis + n);
        float sn = dn * dn;
        float4 acc = bseg;
        fma4(acc, ((const float4*)(hw + (size_t)n * Hdim))[rowOff], sn);

        int j  = __ldg(rowptr + n);
        int e1 = __ldg(rowptr + n + 1);

        for (; j + 3 < e1; j += 4) {
            int2 p0 = __ldg(csr + j);
            int2 p1 = __ldg(csr + j + 1);
            int2 p2 = __ldg(csr + j + 2);
            int2 p3 = __ldg(csr + j + 3);
            float4 v0 = ((const float4*)(hw + (size_t)p0.x * Hdim))[rowOff];
            float4 v1 = ((const float4*)(hw + (size_t)p1.x * Hdim))[rowOff];
            float4 v2 = ((const float4*)(hw + (size_t)p2.x * Hdim))[rowOff];
            float4 v3 = ((const float4*)(hw + (size_t)p3.x * Hdim))[rowOff];
            fma4(acc, v0, __int_as_float(p0.y));
            fma4(acc, v1, __int_as_float(p1.y));
            fma4(acc, v2, __int_as_float(p2.y));
            fma4(acc, v3, __int_as_float(p3.y));
        }
        for (; j < e1; j++) {
            int2 p = __ldg(csr + j);
            float4 v = ((const float4*)(hw + (size_t)p.x * Hdim))[rowOff];
            fma4(acc, v, __int_as_float(p.y));
        }

        ((float4*)(agg + (size_t)n * Hdim))[rowOff] = acc;

        tsum.x += acc.x; tsum.y += acc.y; tsum.z += acc.z; tsum.w += acc.w;
        tsq.x = fmaf(acc.x, acc.x, tsq.x); tsq.y = fmaf(acc.y, acc.y, tsq.y);
        tsq.z = fmaf(acc.z, acc.z, tsq.z); tsq.w = fmaf(acc.w, acc.w, tsq.w);
    }

    sh_s[wid][lane] = tsum;
    sh_q[wid][lane] = tsq;
    __syncthreads();

    int f = tid;
    int f4 = f >> 2, comp = f & 3;
    int hf = f4 >> 5, l = f4 & 31;
    float s = 0.f, q = 0.f;
#pragma unroll
    for (int k = 0; k < 4; k++) {
        int w = hf + 2 * k;
        s += ((const float*)&sh_s[w][l])[comp];
        q += ((const float*)&sh_q[w][l])[comp];
    }
    atomicAdd(&stats[f], (double)s);
    atomicAdd(&stats[Hdim + f], (double)q);
}

// ---------------- bn scale/shift ----------------
__global__ void bn_final_k(const double* __restrict__ stats,
                           const float* __restrict__ gamma, const float* __restrict__ beta,
                           float* __restrict__ scale, float* __restrict__ shift, int N)
{
    int f = threadIdx.x;
    double mean = stats[f] / N;
    double var = stats[Hdim + f] / N - mean * mean;
    float sc = gamma[f] * rsqrtf((float)var + 1e-5f);
    scale[f] = sc;
    shift[f] = beta[f] - (float)mean * sc;
}

// ---------------- global add pool with fused BN affine + ReLU ----------------
__global__ void pool_k(const float* __restrict__ h, const int* __restrict__ batch,
                       const float* __restrict__ scale, const float* __restrict__ shift,
                       float* __restrict__ g, int N)
{
    constexpr int CH = 256;
    int f = threadIdx.x;
    int r0 = blockIdx.x * CH;
    int r1 = min(N, r0 + CH);
    if (r0 >= N) return;
    float sc = scale[f], sh = shift[f];
    int cur = batch[r0];
    float s = 0.f;
    for (int r = r0; r < r1; r++) {
        int b = batch[r];
        if (b != cur) {
            atomicAdd(&g[cur * Hdim + f], s);
            s = 0.f;
            cur = b;
        }
        s += fmaxf(fmaf(h[(size_t)r * Hdim + f], sc, sh), 0.f);
    }
    atomicAdd(&g[cur * Hdim + f], s);
}

// ---------------- MLP head ----------------
__global__ void head_k(const float* __restrict__ g, const float* __restrict__ w1,
                       const float* __restrict__ b1, const float* __restrict__ w2,
                       const float* __restrict__ b2, float* __restrict__ out)
{
    __shared__ float gs[Hdim];
    __shared__ float zs[HD2];
    int b = blockIdx.x;
    int t = threadIdx.x;
    gs[t]       = g[b * Hdim + t];
    gs[t + 128] = g[b * Hdim + t + 128];
    __syncthreads();
    float acc = b1[t];
    for (int k = 0; k < Hdim; k++) acc = fmaf(gs[k], w1[k * HD2 + t], acc);
    zs[t] = fmaxf(acc, 0.f);
    __syncthreads();
    if (t < OUTdim) {
        float o = b2[t];
        for (int k = 0; k < HD2; k++) o = fmaf(zs[k], w2[k * OUTdim + t], o);
        out[b * OUTdim + t] = o;
    }
}

// ---------------- launch ----------------
extern "C" void kernel_launch(void* const* d_in, const int* in_sizes, int n_in,
                              void* d_out, int out_size)
{
    const float* x       = (const float*)d_in[0];
    const int*   ei      = (const int*)d_in[1];
    const int*   batch   = (const int*)d_in[2];
    const float* node_w  = (const float*)d_in[3];
    const float* node_b  = (const float*)d_in[4];
    const float* conv_w  = (const float*)d_in[5];
    const float* conv_b  = (const float*)d_in[6];
    const float* bn_g    = (const float*)d_in[7];
    const float* bn_b    = (const float*)d_in[8];
    const float* head_w1 = (const float*)d_in[9];
    const float* head_b1 = (const float*)d_in[10];
    const float* head_w2 = (const float*)d_in[11];
    const float* head_b2 = (const float*)d_in[12];
    float* out = (float*)d_out;

    int N = in_sizes[0] / INdim;
    int E = in_sizes[1] / 2;
    const int* rowi = ei;
    const int* coli = ei + E;

    float *bufA, *bufB, *dis, *scale, *shift, *pool;
    int *cnt, *rowptr, *cursor, *partial, *bsum;
    int2* csr;
    double* stats;
    __nv_bfloat16 *BtH, *BtL;
    cudaGetSymbolAddress((void**)&bufA, g_bufA);
    cudaGetSymbolAddress((void**)&bufB, g_bufB);
    cudaGetSymbolAddress((void**)&dis, g_dis);
    cudaGetSymbolAddress((void**)&cnt, g_cnt);
    cudaGetSymbolAddress((void**)&rowptr, g_rowptr);
    cudaGetSymbolAddress((void**)&cursor, g_cursor);
    cudaGetSymbolAddress((void**)&partial, g_partial);
    cudaGetSymbolAddress((void**)&bsum, g_bsum);
    cudaGetSymbolAddress((void**)&csr, g_csr);
    cudaGetSymbolAddress((void**)&stats, g_stats);
    cudaGetSymbolAddress((void**)&scale, g_scale);
    cudaGetSymbolAddress((void**)&shift, g_shift);
    cudaGetSymbolAddress((void**)&pool, g_pool);
    cudaGetSymbolAddress((void**)&BtH, g_BtH);
    cudaGetSymbolAddress((void**)&BtL, g_BtL);

    int nblk1 = (N + SCAN_B - 1) / SCAN_B;
    dim3 ggrid(Hdim / GBN, (N + GBM - 1) / GBM);   // (4, 391)

    // 1: zero, 2: weight split, 3: node gemm, 4: conv gemm l0 (profiled slot)
    zero_all_k<<<(N + 255) / 256, 256>>>(cnt, stats, pool, N);
    wsplit_k<<<(WTOT + 255) / 256, 256>>>(node_w, conv_w);
    gemm_tc_k<<<ggrid, 256>>>(x, BtH + NODE_OFF, BtL + NODE_OFF, node_b, bufA,
                              nullptr, nullptr, N, INdim);
    gemm_tc_k<<<ggrid, 256>>>(bufA, BtH + CONV_OFF, BtL + CONV_OFF, nullptr, bufB,
                              nullptr, nullptr, N, Hdim);

    // CSR build
    count_k<<<592, 256>>>(coli, cnt, E);
    scan1_k<<<nblk1, SCAN_B>>>(cnt, partial, bsum, N);
    scan2_k<<<1, SCAN_B>>>(bsum, nblk1);
    scan3_k<<<(N + 255) / 256, 256>>>(partial, bsum, cnt, rowptr, cursor, dis, N, E);
    fill_k<<<592, 256>>>(rowi, coli, dis, cursor, csr, E);

    int aggBlocks = 592;
    // layer 0 tail
    aggregate_k<<<aggBlocks, 256>>>(bufB, bufA, rowptr, csr, dis, conv_b, stats, N);
    bn_final_k<<<1, 256>>>(stats, bn_g, bn_b, scale, shift, N);

    // layers 1..2
    for (int l = 1; l < NLAY; l++) {
        gemm_tc_k<<<ggrid, 256>>>(bufA, BtH + CONV_OFF + l * 65536,
                                  BtL + CONV_OFF + l * 65536, nullptr, bufB,
                                  scale + (l - 1) * Hdim, shift + (l - 1) * Hdim,
                                  N, Hdim);
        aggregate_k<<<aggBlocks, 256>>>(bufB, bufA, rowptr, csr, dis,
                                        conv_b + l * Hdim, stats + l * 2 * Hdim, N);
        bn_final_k<<<1, 256>>>(stats + l * 2 * Hdim, bn_g + l * Hdim, bn_b + l * Hdim,
                               scale + l * Hdim, shift + l * Hdim, N);
    }

    // pool (applies layer-2 BN affine + relu) + head
    pool_k<<<(N + 255) / 256, 256>>>(bufA, batch, scale + 2 * Hdim, shift + 2 * Hdim,
                                     pool, N);
    head_k<<<NGRAPH, HD2>>>(pool, head_w1, head_b1, head_w2, head_b2, out);
}

// round 12
// speedup vs baseline: 1.9337x; 1.1631x over previous
#include <cuda_runtime.h>
#include <cuda_bf16.h>
#include <cstdint>
#include <math.h>

// ---------------- problem constants ----------------
constexpr int Hdim   = 256;
constexpr int INdim  = 64;
constexpr int HD2    = 128;
constexpr int OUTdim = 12;
constexpr int NLAY   = 3;
constexpr int NGRAPH = 64;
constexpr int NMAX   = 50000;
constexpr int EMAX   = 600000;
constexpr int SCAN_B = 512;
constexpr int MAXBLK1 = (NMAX + SCAN_B - 1) / SCAN_B;

// weight scratch: bf16 split + transposed [N][K]
constexpr int NODE_OFF = 0;                      // 256 x 64
constexpr int CONV_OFF = 256 * 64;               // 3 x (256 x 256)
constexpr int WTOT     = CONV_OFF + 3 * 256 * 256;

// ---------------- scratch (device globals, no allocation) ----------------
__device__ float  g_bufA[(size_t)NMAX * Hdim];
__device__ float  g_bufB[(size_t)NMAX * Hdim];
__device__ float  g_dis[NMAX];
__device__ int    g_cnt[NMAX];
__device__ int    g_rowptr[NMAX + 1];
__device__ int    g_cursor[NMAX];
__device__ int    g_partial[NMAX];
__device__ int    g_bsum[MAXBLK1 + 1];
__device__ int2   g_csr[EMAX];
__device__ double g_stats[NLAY * 2 * Hdim];
__device__ float  g_scale[NLAY * Hdim];
__device__ float  g_shift[NLAY * Hdim];
__device__ float  g_pool[NGRAPH * Hdim];
__device__ __nv_bfloat16 g_BtH[WTOT];
__device__ __nv_bfloat16 g_BtL[WTOT];
__device__ __nv_bfloat16 g_pAH[(size_t)NMAX * Hdim];   // split activations (ping)
__device__ __nv_bfloat16 g_pAL[(size_t)NMAX * Hdim];
__device__ __nv_bfloat16 g_qAH[(size_t)NMAX * Hdim];   // split activations (pong)
__device__ __nv_bfloat16 g_qAL[(size_t)NMAX * Hdim];

// ---------------- helpers ----------------
__device__ __forceinline__ uint32_t packbf2(float hi, float lo) {
    uint32_t d;
    asm("cvt.rn.bf16x2.f32 %0, %1, %2;" : "=r"(d) : "f"(hi), "f"(lo));
    return d;
}

// split pair (x0 = lower k, x1 = upper k) into hi/lo bf16x2 words
__device__ __forceinline__ void split2(float x0, float x1, uint32_t& h, uint32_t& l) {
    h = packbf2(x1, x0);
    float f0 = __uint_as_float(h << 16);
    float f1 = __uint_as_float(h & 0xFFFF0000u);
    l = packbf2(x1 - f1, x0 - f0);
}

#define MMA_BF16(d, a, b)                                                       \
    asm volatile("mma.sync.aligned.m16n8k16.row.col.f32.bf16.bf16.f32 "        \
                 "{%0,%1,%2,%3},{%4,%5,%6,%7},{%8,%9},{%0,%1,%2,%3};"          \
                 : "+f"(d[0]), "+f"(d[1]), "+f"(d[2]), "+f"(d[3])              \
                 : "r"(a[0]), "r"(a[1]), "r"(a[2]), "r"(a[3]),                 \
                   "r"(b[0]), "r"(b[1]))

__device__ __forceinline__ void ldsm_x4(uint32_t& r0, uint32_t& r1,
                                        uint32_t& r2, uint32_t& r3, uint32_t addr) {
    asm volatile("ldmatrix.sync.aligned.m8n8.x4.shared.b16 {%0,%1,%2,%3}, [%4];"
                 : "=r"(r0), "=r"(r1), "=r"(r2), "=r"(r3) : "r"(addr));
}

__device__ __forceinline__ void cp16(uint32_t dst, const void* src, uint32_t sz) {
    asm volatile("cp.async.cg.shared.global [%0], [%1], 16, %2;"
                 :: "r"(dst), "l"(src), "r"(sz) : "memory");
}
__device__ __forceinline__ void cp8(uint32_t dst, const void* src) {
    asm volatile("cp.async.ca.shared.global [%0], [%1], 8;"
                 :: "r"(dst), "l"(src) : "memory");
}
#define CP_COMMIT() asm volatile("cp.async.commit_group;" ::: "memory")

// ---------------- weight pre-split+transpose (once per call) ----------------
__global__ void wsplit_k(const float* __restrict__ node_w,
                         const float* __restrict__ conv_w)
{
    int idx = blockIdx.x * blockDim.x + threadIdx.x;
    if (idx >= WTOT) return;
    float v;
    if (idx < CONV_OFF) {                 // node: Bt[n][k], k<64 ; src [k][n]
        int n = idx / INdim, k = idx % INdim;
        v = node_w[k * Hdim + n];
    } else {
        int rel = idx - CONV_OFF;
        int l = rel >> 16;
        int r2 = rel & 65535;
        int n = r2 >> 8, k = r2 & 255;
        v = conv_w[l * 65536 + k * Hdim + n];
    }
    __nv_bfloat16 h = __float2bfloat16(v);
    __nv_bfloat16 lo = __float2bfloat16(v - __bfloat162float(h));
    g_BtH[idx] = h;
    g_BtL[idx] = lo;
}

// ---------------- activation split (+ optional BN affine + relu) --------------
__global__ void asplit_k(const float4* __restrict__ src,
                         const float* __restrict__ scale, const float* __restrict__ shift,
                         uint2* __restrict__ dH, uint2* __restrict__ dL,
                         int n4, int kmask4)
{
    int i = blockIdx.x * blockDim.x + threadIdx.x;
    if (i >= n4) return;
    float4 v = src[i];
    if (scale) {
        int f = (i & kmask4) * 4;
        float4 sc = *(const float4*)(scale + f);
        float4 sh = *(const float4*)(shift + f);
        v.x = fmaxf(fmaf(v.x, sc.x, sh.x), 0.f);
        v.y = fmaxf(fmaf(v.y, sc.y, sh.y), 0.f);
        v.z = fmaxf(fmaf(v.z, sc.z, sh.z), 0.f);
        v.w = fmaxf(fmaf(v.w, sc.w, sh.w), 0.f);
    }
    uint32_t h0, l0, h1, l1;
    split2(v.x, v.y, h0, l0);
    split2(v.z, v.w, h1, l1);
    dH[i] = make_uint2(h0, h1);
    dL[i] = make_uint2(l0, l1);
}

// ---------------- one-shot zeroing ----------------
__global__ void zero_all_k(int* cnt, double* stats, float* pool, int N) {
    int i = blockIdx.x * blockDim.x + threadIdx.x;
    if (i < N) cnt[i] = 0;
    if (i < NLAY * 2 * Hdim) stats[i] = 0.0;
    if (i < NGRAPH * Hdim) pool[i] = 0.0f;
}

// ---------------- CSR build ----------------
__global__ void count_k(const int* __restrict__ coli, int* __restrict__ cnt, int E) {
    int i = blockIdx.x * blockDim.x + threadIdx.x;
    int stride = gridDim.x * blockDim.x;
    for (int e = i; e < E; e += stride) atomicAdd(&cnt[coli[e]], 1);
}

__global__ void scan1_k(const int* __restrict__ cnt, int* __restrict__ partial,
                        int* __restrict__ bsum, int N)
{
    __shared__ int sh[SCAN_B];
    int t = threadIdx.x;
    int i = blockIdx.x * SCAN_B + t;
    int v = (i < N) ? cnt[i] : 0;
    sh[t] = v;
    __syncthreads();
#pragma unroll
    for (int off = 1; off < SCAN_B; off <<= 1) {
        int add = (t >= off) ? sh[t - off] : 0;
        __syncthreads();
        sh[t] += add;
        __syncthreads();
    }
    if (i < N) partial[i] = sh[t] - v;
    if (t == SCAN_B - 1) bsum[blockIdx.x] = sh[t];
}

__global__ void scan2_k(int* __restrict__ bsum, int nb) {
    __shared__ int sh[SCAN_B];
    int t = threadIdx.x;
    int v = (t < nb) ? bsum[t] : 0;
    sh[t] = v;
    __syncthreads();
#pragma unroll
    for (int off = 1; off < SCAN_B; off <<= 1) {
        int add = (t >= off) ? sh[t - off] : 0;
        __syncthreads();
        sh[t] += add;
        __syncthreads();
    }
    if (t < nb) bsum[t] = sh[t] - v;
}

__global__ void scan3_k(const int* __restrict__ partial, const int* __restrict__ bsum,
                        const int* __restrict__ cnt, int* __restrict__ rowptr,
                        int* __restrict__ cursor, float* __restrict__ dis, int N, int E)
{
    int i = blockIdx.x * blockDim.x + threadIdx.x;
    if (i < N) {
        int rp = partial[i] + bsum[i / SCAN_B];
        rowptr[i] = rp;
        cursor[i] = rp;
        dis[i] = rsqrtf((float)(cnt[i] + 1));
    }
    if (i == 0) rowptr[N] = E;
}

__global__ void fill_k(const int* __restrict__ rowi, const int* __restrict__ coli,
                       const float* __restrict__ dis, int* __restrict__ cursor,
                       int2* __restrict__ csr, int E)
{
    int i = blockIdx.x * blockDim.x + threadIdx.x;
    int stride = gridDim.x * blockDim.x;
    for (int e = i; e < E; e += stride) {
        int r = rowi[e], c = coli[e];
        int slot = atomicAdd(&cursor[c], 1);
        csr[slot] = make_int2(r, __float_as_int(dis[r] * dis[c]));
    }
}

// ---------------- tensor-core GEMM (pre-split bf16, cp.async 3-stage) ---------
// C[M,256] = A[M,K] @ W[K,256] (+bias).  A given as split bf16 AH/AL [M][K].
// W pre-split+transposed Bt[n][k].  Output: f32 C, or split bf16 CH/CL.
// Block tile 128x64, 8 warps (4m x 2n), warp tile 32x32, BK=16.
constexpr int GBM = 128, GBN = 64, GBK = 16;
constexpr int PADW = 12;                       // words per row (8 data + 4 pad)
constexpr uint32_t OFF_AH = 0;
constexpr uint32_t OFF_AL = 128 * 48;          // 6144
constexpr uint32_t OFF_BH = 12288;
constexpr uint32_t OFF_BL = 12288 + 64 * 48;   // 15360
constexpr uint32_t STAGE  = 18432;
constexpr int NSTAGE = 3;
constexpr int GSMEM = STAGE * NSTAGE;          // 55296

__global__ __launch_bounds__(256, 3)
void gemm_tc_k(const __nv_bfloat16* __restrict__ AH, const __nv_bfloat16* __restrict__ AL,
               const __nv_bfloat16* __restrict__ BtH, const __nv_bfloat16* __restrict__ BtL,
               const float* __restrict__ bias, float* __restrict__ C,
               __nv_bfloat16* __restrict__ CH, __nv_bfloat16* __restrict__ CL,
               int M, int K)
{
    extern __shared__ __align__(16) uint8_t dsm[];
    uint32_t sb = (uint32_t)__cvta_generic_to_shared(dsm);

    int tid = threadIdx.x;
    int wid = tid >> 5, lane = tid & 31;
    int g = lane >> 2, t4 = lane & 3;
    int wm = wid & 3, wn = wid >> 2;

    int rowBase = blockIdx.y * GBM;
    int colBase = blockIdx.x * GBN;

    float acc[2][4][4];
#pragma unroll
    for (int m = 0; m < 2; m++)
#pragma unroll
        for (int na = 0; na < 4; na++)
#pragma unroll
            for (int c = 0; c < 4; c++) acc[m][na][c] = 0.0f;

    // staging: A thread -> row tid>>1, 8 k (16B) at (tid&1)*8
    int arow = tid >> 1, ahalf = tid & 1;
    uint32_t asz = ((rowBase + arow) < M) ? 16u : 0u;
    const __nv_bfloat16* aphSrc = AH + (size_t)(rowBase + arow) * K + ahalf * 8;
    const __nv_bfloat16* aplSrc = AL + (size_t)(rowBase + arow) * K + ahalf * 8;
    uint32_t aDst = sb + arow * 48 + ahalf * 16;
    // B thread -> n tid>>2, 4 k (8B) at (tid&3)*4
    int bn = tid >> 2, q = tid & 3;
    const __nv_bfloat16* bphSrc = BtH + (size_t)(colBase + bn) * K + q * 4;
    const __nv_bfloat16* bplSrc = BtL + (size_t)(colBase + bn) * K + q * 4;
    uint32_t bDst = sb + bn * 48 + q * 8;

    // ldmatrix fragment lane addressing (constant across k-loop)
    int lr = lane & 7;
    int sel = lane >> 3;
    int aRowF  = wm * 32 + (sel & 1) * 8 + lr;
    int aWordF = (sel >> 1) * 4;
    int bRowF  = wn * 32 + (sel >> 1) * 8 + lr;
    int bWordF = (sel & 1) * 4;
    uint32_t aFH = sb + OFF_AH + (aRowF * PADW + aWordF) * 4;
    uint32_t aFL = sb + OFF_AL + (aRowF * PADW + aWordF) * 4;
    uint32_t bFH = sb + OFF_BH + (bRowF * PADW + bWordF) * 4;
    uint32_t bFL = sb + OFF_BL + (bRowF * PADW + bWordF) * 4;
    constexpr uint32_t A_MSTEP = 16 * 48;
    constexpr uint32_t B_PSTEP = 16 * 48;

    auto issue = [&](int t) {
        uint32_t so = (uint32_t)(t % NSTAGE) * STAGE;
        int k0 = t * GBK;
        cp16(aDst + so + OFF_AH, aphSrc + k0, asz);
        cp16(aDst + so + OFF_AL, aplSrc + k0, asz);
        cp8(bDst + so + OFF_BH, bphSrc + k0);
        cp8(bDst + so + OFF_BL, bplSrc + k0);
        CP_COMMIT();
    };

    int nT = K / GBK;
    issue(0);
    if (nT > 1) issue(1);

    for (int t = 0; t < nT; t++) {
        if (t + 1 < nT) asm volatile("cp.async.wait_group 1;" ::: "memory");
        else            asm volatile("cp.async.wait_group 0;" ::: "memory");
        __syncthreads();
        if (t + 2 < nT) issue(t + 2);

        uint32_t so = (uint32_t)(t % NSTAGE) * STAGE;
        uint32_t aH[2][4], aL[2][4], bHf[4][2], bLf[4][2];
#pragma unroll
        for (int m = 0; m < 2; m++) {
            ldsm_x4(aH[m][0], aH[m][1], aH[m][2], aH[m][3], aFH + so + m * A_MSTEP);
            ldsm_x4(aL[m][0], aL[m][1], aL[m][2], aL[m][3], aFL + so + m * A_MSTEP);
        }
#pragma unroll
        for (int p = 0; p < 2; p++) {
            ldsm_x4(bHf[2 * p][0], bHf[2 * p][1], bHf[2 * p + 1][0], bHf[2 * p + 1][1],
                    bFH + so + p * B_PSTEP);
            ldsm_x4(bLf[2 * p][0], bLf[2 * p][1], bLf[2 * p + 1][0], bLf[2 * p + 1][1],
                    bFL + so + p * B_PSTEP);
        }

        // pass-major: 8 independent MMAs between reuses of each accumulator
#pragma unroll
        for (int m = 0; m < 2; m++)
#pragma unroll
            for (int na = 0; na < 4; na++) MMA_BF16(acc[m][na], aH[m], bHf[na]);
#pragma unroll
        for (int m = 0; m < 2; m++)
#pragma unroll
            for (int na = 0; na < 4; na++) MMA_BF16(acc[m][na], aH[m], bLf[na]);
#pragma unroll
        for (int m = 0; m < 2; m++)
#pragma unroll
            for (int na = 0; na < 4; na++) MMA_BF16(acc[m][na], aL[m], bHf[na]);
    }

    // epilogue
#pragma unroll
    for (int m = 0; m < 2; m++) {
        int r0 = rowBase + wm * 32 + m * 16 + g;
#pragma unroll
        for (int na = 0; na < 4; na++) {
            int col = colBase + wn * 32 + na * 8 + 2 * t4;
            float b0 = 0.f, b1 = 0.f;
            if (bias) { b0 = bias[col]; b1 = bias[col + 1]; }
            float v0 = acc[m][na][0] + b0, v1 = acc[m][na][1] + b1;
            float v2 = acc[m][na][2] + b0, v3 = acc[m][na][3] + b1;
            if (CH) {   // split bf16 output
                uint32_t h, l;
                if (r0 < M) {
                    split2(v0, v1, h, l);
                    size_t w = ((size_t)r0 * Hdim + col) >> 1;
                    ((uint32_t*)CH)[w] = h;
                    ((uint32_t*)CL)[w] = l;
                }
                if (r0 + 8 < M) {
                    split2(v2, v3, h, l);
                    size_t w = ((size_t)(r0 + 8) * Hdim + col) >> 1;
                    ((uint32_t*)CH)[w] = h;
                    ((uint32_t*)CL)[w] = l;
                }
            } else {
                if (r0 < M)
                    *(float2*)&C[(size_t)r0 * Hdim + col] = make_float2(v0, v1);
                if (r0 + 8 < M)
                    *(float2*)&C[(size_t)(r0 + 8) * Hdim + col] = make_float2(v2, v3);
            }
        }
    }
}

// ---------------- aggregate v2: 2 warps/node, packed csr, fused BN stats -------
__device__ __forceinline__ void fma4(float4& a, const float4& v, float s) {
    a.x = fmaf(v.x, s, a.x); a.y = fmaf(v.y, s, a.y);
    a.z = fmaf(v.z, s, a.z); a.w = fmaf(v.w, s, a.w);
}

__global__ __launch_bounds__(256)
void aggregate_k(const float* __restrict__ hw, float* __restrict__ agg,
                 const int* __restrict__ rowptr, const int2* __restrict__ csr,
                 const float* __restrict__ dis,
                 const float* __restrict__ convb, double* __restrict__ stats, int N)
{
    __shared__ float4 sh_s[8][32];
    __shared__ float4 sh_q[8][32];

    int tid = threadIdx.x;
    int wid = tid >> 5;
    int lane = tid & 31;

    int gw = blockIdx.x * 8 + wid;
    int half = gw & 1;
    int rowOff = half * 32 + lane;

    float4 bseg = ((const float4*)convb)[rowOff];
    float4 tsum = make_float4(0, 0, 0, 0);
    float4 tsq  = make_float4(0, 0, 0, 0);

    int nodeStride = gridDim.x * 4;

    for (int n = gw >> 1; n < N; n += nodeStride) {
        float dn = __ldg(dis + n);
        float sn = dn * dn;
        float4 acc = bseg;
        fma4(acc, ((const float4*)(hw + (size_t)n * Hdim))[rowOff], sn);

        int j  = __ldg(rowptr + n);
        int e1 = __ldg(rowptr + n + 1);

        for (; j + 3 < e1; j += 4) {
            int2 p0 = __ldg(csr + j);
            int2 p1 = __ldg(csr + j + 1);
            int2 p2 = __ldg(csr + j + 2);
            int2 p3 = __ldg(csr + j + 3);
            float4 v0 = ((const float4*)(hw + (size_t)p0.x * Hdim))[rowOff];
            float4 v1 = ((const float4*)(hw + (size_t)p1.x * Hdim))[rowOff];
            float4 v2 = ((const float4*)(hw + (size_t)p2.x * Hdim))[rowOff];
            float4 v3 = ((const float4*)(hw + (size_t)p3.x * Hdim))[rowOff];
            fma4(acc, v0, __int_as_float(p0.y));
            fma4(acc, v1, __int_as_float(p1.y));
            fma4(acc, v2, __int_as_float(p2.y));
            fma4(acc, v3, __int_as_float(p3.y));
        }
        for (; j < e1; j++) {
            int2 p = __ldg(csr + j);
            float4 v = ((const float4*)(hw + (size_t)p.x * Hdim))[rowOff];
            fma4(acc, v, __int_as_float(p.y));
        }

        ((float4*)(agg + (size_t)n * Hdim))[rowOff] = acc;

        tsum.x += acc.x; tsum.y += acc.y; tsum.z += acc.z; tsum.w += acc.w;
        tsq.x = fmaf(acc.x, acc.x, tsq.x); tsq.y = fmaf(acc.y, acc.y, tsq.y);
        tsq.z = fmaf(acc.z, acc.z, tsq.z); tsq.w = fmaf(acc.w, acc.w, tsq.w);
    }

    sh_s[wid][lane] = tsum;
    sh_q[wid][lane] = tsq;
    __syncthreads();

    int f = tid;
    int f4 = f >> 2, comp = f & 3;
    int hf = f4 >> 5, l = f4 & 31;
    float s = 0.f, q = 0.f;
#pragma unroll
    for (int k = 0; k < 4; k++) {
        int w = hf + 2 * k;
        s += ((const float*)&sh_s[w][l])[comp];
        q += ((const float*)&sh_q[w][l])[comp];
    }
    atomicAdd(&stats[f], (double)s);
    atomicAdd(&stats[Hdim + f], (double)q);
}

// ---------------- bn scale/shift ----------------
__global__ void bn_final_k(const double* __restrict__ stats,
                           const float* __restrict__ gamma, const float* __restrict__ beta,
                           float* __restrict__ scale, float* __restrict__ shift, int N)
{
    int f = threadIdx.x;
    double mean = stats[f] / N;
    double var = stats[Hdim + f] / N - mean * mean;
    float sc = gamma[f] * rsqrtf((float)var + 1e-5f);
    scale[f] = sc;
    shift[f] = beta[f] - (float)mean * sc;
}

// ---------------- global add pool with fused BN affine + ReLU ----------------
__global__ void pool_k(const float* __restrict__ h, const int* __restrict__ batch,
                       const float* __restrict__ scale, const float* __restrict__ shift,
                       float* __restrict__ g, int N)
{
    constexpr int CH = 256;
    int f = threadIdx.x;
    int r0 = blockIdx.x * CH;
    int r1 = min(N, r0 + CH);
    if (r0 >= N) return;
    float sc = scale[f], sh = shift[f];
    int cur = batch[r0];
    float s = 0.f;
    for (int r = r0; r < r1; r++) {
        int b = batch[r];
        if (b != cur) {
            atomicAdd(&g[cur * Hdim + f], s);
            s = 0.f;
            cur = b;
        }
        s += fmaxf(fmaf(h[(size_t)r * Hdim + f], sc, sh), 0.f);
    }
    atomicAdd(&g[cur * Hdim + f], s);
}

// ---------------- MLP head ----------------
__global__ void head_k(const float* __restrict__ g, const float* __restrict__ w1,
                       const float* __restrict__ b1, const float* __restrict__ w2,
                       const float* __restrict__ b2, float* __restrict__ out)
{
    __shared__ float gs[Hdim];
    __shared__ float zs[HD2];
    int b = blockIdx.x;
    int t = threadIdx.x;
    gs[t]       = g[b * Hdim + t];
    gs[t + 128] = g[b * Hdim + t + 128];
    __syncthreads();
    float acc = b1[t];
    for (int k = 0; k < Hdim; k++) acc = fmaf(gs[k], w1[k * HD2 + t], acc);
    zs[t] = fmaxf(acc, 0.f);
    __syncthreads();
    if (t < OUTdim) {
        float o = b2[t];
        for (int k = 0; k < HD2; k++) o = fmaf(zs[k], w2[k * OUTdim + t], o);
        out[b * OUTdim + t] = o;
    }
}

// ---------------- launch ----------------
extern "C" void kernel_launch(void* const* d_in, const int* in_sizes, int n_in,
                              void* d_out, int out_size)
{
    const float* x       = (const float*)d_in[0];
    const int*   ei      = (const int*)d_in[1];
    const int*   batch   = (const int*)d_in[2];
    const float* node_w  = (const float*)d_in[3];
    const float* node_b  = (const float*)d_in[4];
    const float* conv_w  = (const float*)d_in[5];
    const float* conv_b  = (const float*)d_in[6];
    const float* bn_g    = (const float*)d_in[7];
    const float* bn_b    = (const float*)d_in[8];
    const float* head_w1 = (const float*)d_in[9];
    const float* head_b1 = (const float*)d_in[10];
    const float* head_w2 = (const float*)d_in[11];
    const float* head_b2 = (const float*)d_in[12];
    float* out = (float*)d_out;

    int N = in_sizes[0] / INdim;
    int E = in_sizes[1] / 2;
    const int* rowi = ei;
    const int* coli = ei + E;

    float *bufA, *bufB, *dis, *scale, *shift, *pool;
    int *cnt, *rowptr, *cursor, *partial, *bsum;
    int2* csr;
    double* stats;
    __nv_bfloat16 *BtH, *BtL, *pAH, *pAL, *qAH, *qAL;
    cudaGetSymbolAddress((void**)&bufA, g_bufA);
    cudaGetSymbolAddress((void**)&bufB, g_bufB);
    cudaGetSymbolAddress((void**)&dis, g_dis);
    cudaGetSymbolAddress((void**)&cnt, g_cnt);
    cudaGetSymbolAddress((void**)&rowptr, g_rowptr);
    cudaGetSymbolAddress((void**)&cursor, g_cursor);
    cudaGetSymbolAddress((void**)&partial, g_partial);
    cudaGetSymbolAddress((void**)&bsum, g_bsum);
    cudaGetSymbolAddress((void**)&csr, g_csr);
    cudaGetSymbolAddress((void**)&stats, g_stats);
    cudaGetSymbolAddress((void**)&scale, g_scale);
    cudaGetSymbolAddress((void**)&shift, g_shift);
    cudaGetSymbolAddress((void**)&pool, g_pool);
    cudaGetSymbolAddress((void**)&BtH, g_BtH);
    cudaGetSymbolAddress((void**)&BtL, g_BtL);
    cudaGetSymbolAddress((void**)&pAH, g_pAH);
    cudaGetSymbolAddress((void**)&pAL, g_pAL);
    cudaGetSymbolAddress((void**)&qAH, g_qAH);
    cudaGetSymbolAddress((void**)&qAL, g_qAL);

    static int smemSet = 0;
    if (!smemSet) {
        cudaFuncSetAttribute(gemm_tc_k, cudaFuncAttributeMaxDynamicSharedMemorySize, GSMEM);
        smemSet = 1;
    }

    int nblk1 = (N + SCAN_B - 1) / SCAN_B;
    dim3 ggrid(Hdim / GBN, (N + GBM - 1) / GBM);   // (4, 391)

    // prep
    zero_all_k<<<(N + 255) / 256, 256>>>(cnt, stats, pool, N);
    wsplit_k<<<(WTOT + 255) / 256, 256>>>(node_w, conv_w);
    asplit_k<<<(N * 16 + 255) / 256, 256>>>((const float4*)x, nullptr, nullptr,
                                            (uint2*)pAH, (uint2*)pAL, N * 16, 15);
    // node embedding: h0 = x @ node_w + node_b -> split bf16 (q pair)
    gemm_tc_k<<<ggrid, 256, GSMEM>>>(pAH, pAL, BtH + NODE_OFF, BtL + NODE_OFF,
                                     node_b, nullptr, qAH, qAL, N, INdim);
    // conv l0: hw = h0 @ W0 -> bufB
    gemm_tc_k<<<ggrid, 256, GSMEM>>>(qAH, qAL, BtH + CONV_OFF, BtL + CONV_OFF,
                                     nullptr, bufB, nullptr, nullptr, N, Hdim);

    // CSR build
    count_k<<<592, 256>>>(coli, cnt, E);
    scan1_k<<<nblk1, SCAN_B>>>(cnt, partial, bsum, N);
    scan2_k<<<1, SCAN_B>>>(bsum, nblk1);
    scan3_k<<<(N + 255) / 256, 256>>>(partial, bsum, cnt, rowptr, cursor, dis, N, E);
    fill_k<<<592, 256>>>(rowi, coli, dis, cursor, csr, E);

    int aggBlocks = 592;
    // layer 0 tail
    aggregate_k<<<aggBlocks, 256>>>(bufB, bufA, rowptr, csr, dis, conv_b, stats, N);
    bn_final_k<<<1, 256>>>(stats, bn_g, bn_b, scale, shift, N);

    // layers 1..2
    for (int l = 1; l < NLAY; l++) {
        asplit_k<<<(N * 64 + 255) / 256, 256>>>((const float4*)bufA,
                                                scale + (l - 1) * Hdim, shift + (l - 1) * Hdim,
                                                (uint2*)pAH, (uint2*)pAL, N * 64, 63);
        gemm_tc_k<<<ggrid, 256, GSMEM>>>(pAH, pAL,
                                         BtH + CONV_OFF + l * 65536, BtL + CONV_OFF + l * 65536,
                                         nullptr, bufB, nullptr, nullptr, N, Hdim);
        aggregate_k<<<aggBlocks, 256>>>(bufB, bufA, rowptr, csr, dis,
                                        conv_b + l * Hdim, stats + l * 2 * Hdim, N);
        bn_final_k<<<1, 256>>>(stats + l * 2 * Hdim, bn_g + l * Hdim, bn_b + l * Hdim,
                               scale + l * Hdim, shift + l * Hdim, N);
    }

    // pool (applies layer-2 BN affine + relu) + head
    pool_k<<<(N + 255) / 256, 256>>>(bufA, batch, scale + 2 * Hdim, shift + 2 * Hdim,
                                     pool, N);
    head_k<<<NGRAPH, HD2>>>(pool, head_w1, head_b1, head_w2, head_b2, out);
}